// round 12
// baseline (speedup 1.0000x reference)
#include <cuda_runtime.h>
#include <cuda_bf16.h>
#include <cstdint>
#include <cstddef>

// ---------------------------------------------------------------------------
// Problem constants
// ---------------------------------------------------------------------------
constexpr int Bc = 256;
constexpr int Tc = 128;
constexpr int Dc = 1024;
constexpr int Hc = 1024;
constexpr int Gc = 3 * Hc;        // 3072
constexpr int M1 = Bc * Tc;       // 32768
constexpr int Kc = 1024;

// ---------------------------------------------------------------------------
// Device scratch (static: no cudaMalloc allowed)
// ---------------------------------------------------------------------------
__device__ float         g_gi[(size_t)M1 * Gc];          // x @ W_ih^T + b_ih
__device__ __nv_bfloat16 g_h_hi[2][Bc * Hc];             // double-buffered masked h
__device__ __nv_bfloat16 g_h_lo[2][Bc * Hc];
__device__ __nv_bfloat16 g_x_hi[(size_t)M1 * Dc];
__device__ __nv_bfloat16 g_x_lo[(size_t)M1 * Dc];
__device__ __nv_bfloat16 g_wih_hi[(size_t)Gc * Dc];
__device__ __nv_bfloat16 g_wih_lo[(size_t)Gc * Dc];
__device__ __nv_bfloat16 g_whh_hi[(size_t)Gc * Hc];
__device__ __nv_bfloat16 g_whh_lo[(size_t)Gc * Hc];
__device__ float         g_mask[M1];                     // (~is_init) as float
__device__ int           g_mode;                         // 0=int32, 1=bool8, 2=float32
__device__ unsigned      g_epoch[4];                     // per-mi-group barrier epochs

// ---------------------------------------------------------------------------
// PTX helpers
// ---------------------------------------------------------------------------
__device__ __forceinline__ void cp16(uint32_t s, const void* g) {
    asm volatile("cp.async.cg.shared.global [%0], [%1], 16;" :: "r"(s), "l"(g));
}
__device__ __forceinline__ void ldsm4(uint32_t& r0, uint32_t& r1, uint32_t& r2, uint32_t& r3, uint32_t a) {
    asm volatile("ldmatrix.sync.aligned.m8n8.x4.shared.b16 {%0,%1,%2,%3}, [%4];"
                 : "=r"(r0), "=r"(r1), "=r"(r2), "=r"(r3) : "r"(a));
}
__device__ __forceinline__ void mma16816(float* c, const uint32_t* a, const uint32_t* b) {
    asm volatile("mma.sync.aligned.m16n8k16.row.col.f32.bf16.bf16.f32 "
                 "{%0,%1,%2,%3}, {%4,%5,%6,%7}, {%8,%9}, {%0,%1,%2,%3};"
                 : "+f"(c[0]), "+f"(c[1]), "+f"(c[2]), "+f"(c[3])
                 : "r"(a[0]), "r"(a[1]), "r"(a[2]), "r"(a[3]), "r"(b[0]), "r"(b[1]));
}

// ---------------------------------------------------------------------------
// Split-bf16 GEMM for gi:  C = (Ahi+Alo)[M,K] * (Bhi+Blo)[N,K]^T + bias
// (unchanged from R9/R11 passing kernel)
// ---------------------------------------------------------------------------
template<int BM, int BN, int WMS, int WNS>
__global__ void __launch_bounds__(WMS * WNS * 32)
gemm_split(const __nv_bfloat16* __restrict__ Ahi, const __nv_bfloat16* __restrict__ Alo,
           const __nv_bfloat16* __restrict__ Bhi, const __nv_bfloat16* __restrict__ Blo,
           const float* __restrict__ bias, float* __restrict__ C,
           int M, int N, int K)
{
    constexpr int NTHR  = WMS * WNS * 32;
    constexpr int WM    = BM / WMS;
    constexpr int WN    = BN / WNS;
    constexpr int MT    = WM / 16;
    constexpr int NT    = WN / 8;
    constexpr int LD    = 40;
    constexpr int TA    = BM * LD;
    constexpr int TB    = BN * LD;
    constexpr int STAGE = 2 * TA + 2 * TB;

    extern __shared__ __align__(16) __nv_bfloat16 smem[];

    const int tid  = threadIdx.x;
    const int lane = tid & 31;
    const int wid  = tid >> 5;
    const int wm   = wid / WNS;
    const int wn   = wid % WNS;
    const int tM   = blockIdx.y * BM;
    const int tN   = blockIdx.x * BN;
    const uint32_t sbase = (uint32_t)__cvta_generic_to_shared(smem);

    auto issue = [&](int kt, int st) {
        const int k0 = kt * 32;
        uint32_t aHi = sbase + (uint32_t)(st * STAGE) * 2u;
        uint32_t aLo = aHi + TA * 2;
        uint32_t bHi = aLo + TA * 2;
        uint32_t bLo = bHi + TB * 2;
        for (int c = tid; c < BM * 4; c += NTHR) {
            int r = c >> 2, q = c & 3;
            size_t go = (size_t)(tM + r) * K + k0 + q * 8;
            uint32_t so = (uint32_t)(r * LD + q * 8) * 2u;
            cp16(aHi + so, Ahi + go);
            cp16(aLo + so, Alo + go);
        }
        for (int c = tid; c < BN * 4; c += NTHR) {
            int r = c >> 2, q = c & 3;
            size_t go = (size_t)(tN + r) * K + k0 + q * 8;
            uint32_t so = (uint32_t)(r * LD + q * 8) * 2u;
            cp16(bHi + so, Bhi + go);
            cp16(bLo + so, Blo + go);
        }
        asm volatile("cp.async.commit_group;");
    };

    float acc[MT][NT][4];
#pragma unroll
    for (int i = 0; i < MT; i++)
#pragma unroll
        for (int j = 0; j < NT; j++)
#pragma unroll
            for (int k = 0; k < 4; k++) acc[i][j][k] = 0.f;

    const int NKT = K / 32;
    issue(0, 0);

    for (int kt = 0; kt < NKT; kt++) {
        const int st = kt & 1;
        if (kt + 1 < NKT) {
            issue(kt + 1, st ^ 1);
            asm volatile("cp.async.wait_group 1;");
        } else {
            asm volatile("cp.async.wait_group 0;");
        }
        __syncthreads();

        uint32_t aHi = sbase + (uint32_t)(st * STAGE) * 2u;
        uint32_t aLo = aHi + TA * 2;
        uint32_t bHi = aLo + TA * 2;
        uint32_t bLo = bHi + TB * 2;

#pragma unroll
        for (int kk = 0; kk < 32; kk += 16) {
            uint32_t ah[MT][4], al[MT][4];
#pragma unroll
            for (int mt = 0; mt < MT; mt++) {
                int row = wm * WM + mt * 16 + (lane & 7) + ((lane >> 3) & 1) * 8;
                int col = kk + (lane >> 4) * 8;
                uint32_t off = (uint32_t)(row * LD + col) * 2u;
                ldsm4(ah[mt][0], ah[mt][1], ah[mt][2], ah[mt][3], aHi + off);
                ldsm4(al[mt][0], al[mt][1], al[mt][2], al[mt][3], aLo + off);
            }
            uint32_t bh[NT][2], bl[NT][2];
#pragma unroll
            for (int p = 0; p < NT / 2; p++) {
                int nrow = wn * WN + p * 16 + ((lane >> 4) << 3) + (lane & 7);
                int kcol = kk + ((lane >> 3) & 1) * 8;
                uint32_t off = (uint32_t)(nrow * LD + kcol) * 2u;
                ldsm4(bh[2 * p][0], bh[2 * p][1], bh[2 * p + 1][0], bh[2 * p + 1][1], bHi + off);
                ldsm4(bl[2 * p][0], bl[2 * p][1], bl[2 * p + 1][0], bl[2 * p + 1][1], bLo + off);
            }
#pragma unroll
            for (int mt = 0; mt < MT; mt++)
#pragma unroll
                for (int nt = 0; nt < NT; nt++) {
                    mma16816(acc[mt][nt], ah[mt], bh[nt]);
                    mma16816(acc[mt][nt], ah[mt], bl[nt]);
                    mma16816(acc[mt][nt], al[mt], bh[nt]);
                }
        }
        __syncthreads();
    }

#pragma unroll
    for (int mt = 0; mt < MT; mt++) {
#pragma unroll
        for (int nt = 0; nt < NT; nt++) {
            int gr = tM + wm * WM + mt * 16 + (lane >> 2);
            int gc = tN + wn * WN + nt * 8 + (lane & 3) * 2;
            float b0 = bias[gc], b1 = bias[gc + 1];
            float2 v0 = make_float2(acc[mt][nt][0] + b0, acc[mt][nt][1] + b1);
            float2 v1 = make_float2(acc[mt][nt][2] + b0, acc[mt][nt][3] + b1);
            *reinterpret_cast<float2*>(C + (size_t)gr * N + gc)       = v0;
            *reinterpret_cast<float2*>(C + (size_t)(gr + 8) * N + gc) = v1;
        }
    }
}

// ---------------------------------------------------------------------------
// PERSISTENT fused recurrence kernel.
// Grid = 128 CTAs (<=148 SMs -> all co-resident; software barrier is safe).
// CTA (mi, ni): mi = blockIdx.x>>5 owns batch rows [64*mi, 64*mi+64);
//               ni = blockIdx.x&31 owns h-cols [32*ni, 32*ni+32).
// B-tile (96 rows) gathers W_hh rows {g*1024 + 32*ni + j : g in 0..2, j in 0..31}
// so r/z/n for each owned h-index are all inside this CTA -> fused pointwise
// epilogue. One epoch barrier per step per mi-group (groups are independent:
// batch rows never mix). h is double-buffered (bf16 hi/lo).
// ---------------------------------------------------------------------------
__global__ void __launch_bounds__(256, 1)
gru_persistent(const float* __restrict__ gi,
               const __nv_bfloat16* __restrict__ Whi,
               const __nv_bfloat16* __restrict__ Wlo,
               const float* __restrict__ b_hh,
               float* __restrict__ Hseq)
{
    constexpr int LD    = 40;
    constexpr int TA    = 64 * LD;             // 2560 elems
    constexpr int TB    = 96 * LD;             // 3840 elems
    constexpr int STAGE = 2 * TA + 2 * TB;     // 12800 elems per stage
    constexpr int NKT   = Kc / 32;             // 32
    constexpr int CLD   = 104;                 // fp32 C-tile row stride (8B-aligned float2)

    extern __shared__ __align__(16) __nv_bfloat16 smem[];
    float* Cs = reinterpret_cast<float*>(smem);   // reused after the k-loop

    const int tid  = threadIdx.x;
    const int lane = tid & 31;
    const int wid  = tid >> 5;
    const int wm   = wid >> 1;                 // 4 x 2 warps: WM=16, WN=48
    const int wn   = wid & 1;
    const int mi   = blockIdx.x >> 5;
    const int ni   = blockIdx.x & 31;
    const int m0   = mi * 64;
    const int j0   = ni * 32;
    const uint32_t sbase = (uint32_t)__cvta_generic_to_shared(smem);

    int buf = 0;
    for (int t = 0; t < Tc; t++) {
        const __nv_bfloat16* Ahi = g_h_hi[buf];
        const __nv_bfloat16* Alo = g_h_lo[buf];

        auto issue = [&](int kt, int st) {
            const int k0 = kt * 32;
            uint32_t aHi = sbase + (uint32_t)(st * STAGE) * 2u;
            uint32_t aLo = aHi + TA * 2;
            uint32_t bHi = aLo + TA * 2;
            uint32_t bLo = bHi + TB * 2;
            // A: 64 rows * 4 chunks = 256 tasks; B: 96 rows * 4 = 384 tasks
            for (int c = tid; c < 640; c += 256) {
                if (c < 256) {
                    int r = c >> 2, q = c & 3;
                    size_t go = (size_t)(m0 + r) * Kc + k0 + q * 8;
                    uint32_t so = (uint32_t)(r * LD + q * 8) * 2u;
                    cp16(aHi + so, Ahi + go);
                    cp16(aLo + so, Alo + go);
                } else {
                    int cc = c - 256;
                    int r = cc >> 2, q = cc & 3;       // r in [0,96)
                    int g = r >> 5, jj = r & 31;       // gate, h-offset
                    size_t go = (size_t)(g * Hc + j0 + jj) * Kc + k0 + q * 8;
                    uint32_t so = (uint32_t)(r * LD + q * 8) * 2u;
                    cp16(bHi + so, Whi + go);
                    cp16(bLo + so, Wlo + go);
                }
            }
            asm volatile("cp.async.commit_group;");
        };

        float acc[6][4];
#pragma unroll
        for (int j = 0; j < 6; j++)
#pragma unroll
            for (int k = 0; k < 4; k++) acc[j][k] = 0.f;

        issue(0, 0);
        issue(1, 1);

        for (int kt = 0; kt < NKT; kt++) {
            const int st = kt % 3;
            if (kt + 2 < NKT) {
                issue(kt + 2, (kt + 2) % 3);
                asm volatile("cp.async.wait_group 2;");
            } else if (kt + 1 < NKT) {
                asm volatile("cp.async.wait_group 1;");
            } else {
                asm volatile("cp.async.wait_group 0;");
            }
            __syncthreads();

            uint32_t aHi = sbase + (uint32_t)(st * STAGE) * 2u;
            uint32_t aLo = aHi + TA * 2;
            uint32_t bHi = aLo + TA * 2;
            uint32_t bLo = bHi + TB * 2;

#pragma unroll
            for (int kk = 0; kk < 32; kk += 16) {
                uint32_t ah[4], al[4];
                {
                    int row = wm * 16 + (lane & 7) + ((lane >> 3) & 1) * 8;
                    int col = kk + (lane >> 4) * 8;
                    uint32_t off = (uint32_t)(row * LD + col) * 2u;
                    ldsm4(ah[0], ah[1], ah[2], ah[3], aHi + off);
                    ldsm4(al[0], al[1], al[2], al[3], aLo + off);
                }
                uint32_t bh[6][2], bl[6][2];
#pragma unroll
                for (int p = 0; p < 3; p++) {
                    int nrow = wn * 48 + p * 16 + ((lane >> 4) << 3) + (lane & 7);
                    int kcol = kk + ((lane >> 3) & 1) * 8;
                    uint32_t off = (uint32_t)(nrow * LD + kcol) * 2u;
                    ldsm4(bh[2 * p][0], bh[2 * p][1], bh[2 * p + 1][0], bh[2 * p + 1][1], bHi + off);
                    ldsm4(bl[2 * p][0], bl[2 * p][1], bl[2 * p + 1][0], bl[2 * p + 1][1], bLo + off);
                }
#pragma unroll
                for (int nt = 0; nt < 6; nt++) {
                    mma16816(acc[nt], ah, bh[nt]);   // hi*hi
                    mma16816(acc[nt], ah, bl[nt]);   // hi*lo
                    mma16816(acc[nt], al, bh[nt]);   // lo*hi
                }
            }
            __syncthreads();
        }

        // ---- fused epilogue: acc -> smem C tile -> gates -> h update ----
#pragma unroll
        for (int nt = 0; nt < 6; nt++) {
            int rr = wm * 16 + (lane >> 2);
            int gc = wn * 48 + nt * 8 + (lane & 3) * 2;
            *reinterpret_cast<float2*>(&Cs[rr * CLD + gc])       = make_float2(acc[nt][0], acc[nt][1]);
            *reinterpret_cast<float2*>(&Cs[(rr + 8) * CLD + gc]) = make_float2(acc[nt][2], acc[nt][3]);
        }
        __syncthreads();

#pragma unroll
        for (int i = 0; i < 8; i++) {
            int e  = tid + i * 256;          // [0, 2048)
            int rr = e >> 5, jj = e & 31;
            int b  = m0 + rr, j = j0 + jj;

            size_t gib = ((size_t)b * Tc + t) * Gc + j;
            float ir  = gi[gib];
            float iz  = gi[gib + Hc];
            float inn = gi[gib + 2 * Hc];

            float hr = Cs[rr * CLD + jj]      + b_hh[j];
            float hz = Cs[rr * CLD + 32 + jj] + b_hh[Hc + j];
            float hn = Cs[rr * CLD + 64 + jj] + b_hh[2 * Hc + j];

            size_t hidx = (size_t)b * Hc + j;
            float h = __bfloat162float(g_h_hi[buf][hidx]) + __bfloat162float(g_h_lo[buf][hidx]);

            float r = 1.f / (1.f + expf(-(ir + hr)));
            float z = 1.f / (1.f + expf(-(iz + hz)));
            float n = tanhf(inn + r * hn);
            float hnew = (1.f - z) * n + z * h;

            Hseq[((size_t)b * Tc + t) * Hc + j] = hnew;

            float m  = (t + 1 < Tc) ? g_mask[b * Tc + t + 1] : 0.f;
            float hm = hnew * m;
            __nv_bfloat16 hh = __float2bfloat16(hm);
            g_h_hi[buf ^ 1][hidx] = hh;
            g_h_lo[buf ^ 1][hidx] = __float2bfloat16(hm - __bfloat162float(hh));
        }

        // ---- per-group grid barrier (32 CTAs share batch rows of mi) ----
        if (t + 1 < Tc) {
            __syncthreads();
            if (tid == 0) {
                __threadfence();                       // publish h writes
                atomicAdd(&g_epoch[mi], 1u);
                unsigned want = 32u * (unsigned)(t + 1);
                while (atomicAdd(&g_epoch[mi], 0u) < want) __nanosleep(64);
                __threadfence();                       // acquire peers' h writes
            }
            __syncthreads();
        }
        buf ^= 1;
    }
}

// ---------------------------------------------------------------------------
// Mask dtype detection (is_init may be bool8 / int32 / float32)
// ---------------------------------------------------------------------------
__global__ void detect_kernel(const unsigned char* __restrict__ p) {
    __shared__ int nz_off, f3;
    if (threadIdx.x == 0) { nz_off = 0; f3 = 0; }
    __syncthreads();
    int local_nz = 0, local_f3 = 0;
    for (int i = threadIdx.x; i < M1; i += blockDim.x) {
        unsigned char c = p[i];
        if ((i & 3) != 0 && c) local_nz = 1;
        if ((i & 3) == 3 && c == 0x3F) local_f3 = 1;
    }
    if (local_nz) atomicOr(&nz_off, 1);
    if (local_f3) atomicOr(&f3, 1);
    __syncthreads();
    if (threadIdx.x == 0) g_mode = (!nz_off) ? 0 : (f3 ? 2 : 1);
}

__global__ void mask_kernel(const void* __restrict__ p) {
    int i = blockIdx.x * blockDim.x + threadIdx.x;
    if (i >= M1) return;
    int mode = g_mode;
    int v;
    if (mode == 0)      v = (((const int*)p)[i] != 0);
    else if (mode == 1) v = (((const unsigned char*)p)[i] != 0);
    else                v = (((const float*)p)[i] != 0.f);
    g_mask[i] = v ? 0.f : 1.f;
}

__global__ void bar_init_kernel() {
    if (threadIdx.x < 4) g_epoch[threadIdx.x] = 0u;
}

// ---------------------------------------------------------------------------
// fp32 -> (bf16 hi, bf16 lo) split
// ---------------------------------------------------------------------------
__global__ void split_f32(const float* __restrict__ src,
                          __nv_bfloat16* __restrict__ hi, __nv_bfloat16* __restrict__ lo,
                          long n) {
    long stride = (long)gridDim.x * blockDim.x;
    for (long i = (long)blockIdx.x * blockDim.x + threadIdx.x; i < n; i += stride) {
        float v = src[i];
        __nv_bfloat16 h = __float2bfloat16(v);
        hi[i] = h;
        lo[i] = __float2bfloat16(v - __bfloat162float(h));
    }
}

// ---------------------------------------------------------------------------
// h0 = hx * mask[:,0] -> buffer 0 (bf16 hi/lo)
// ---------------------------------------------------------------------------
__global__ void init_h_kernel(const float* __restrict__ hx) {
    int idx = blockIdx.x * blockDim.x + threadIdx.x;
    if (idx >= Bc * Hc) return;
    int b = idx >> 10;
    float v = hx[idx] * g_mask[(size_t)b * Tc + 0];
    __nv_bfloat16 h = __float2bfloat16(v);
    g_h_hi[0][idx] = h;
    g_h_lo[0][idx] = __float2bfloat16(v - __bfloat162float(h));
}

// ---------------------------------------------------------------------------
// Y = LN(Hseq)*g + b + x*sigmoid(res_gate)
// ---------------------------------------------------------------------------
__global__ void ln_kernel(const float* __restrict__ Hseq, const float* __restrict__ x,
                          const float* __restrict__ gg, const float* __restrict__ bb,
                          const float* __restrict__ res_gate, float* __restrict__ Y) {
    int m = blockIdx.x;
    const float* row = Hseq + (size_t)m * Hc;
    int tid = threadIdx.x;
    int lane = tid & 31, wid = tid >> 5;

    float v[8];
    float s = 0.f, s2 = 0.f;
#pragma unroll
    for (int i = 0; i < 8; i++) {
        float t = row[tid + i * 128];
        v[i] = t; s += t; s2 += t * t;
    }
#pragma unroll
    for (int o = 16; o; o >>= 1) {
        s  += __shfl_xor_sync(0xffffffffu, s, o);
        s2 += __shfl_xor_sync(0xffffffffu, s2, o);
    }
    __shared__ float red[8];
    if (lane == 0) { red[wid] = s; red[4 + wid] = s2; }
    __syncthreads();
    float ts  = red[0] + red[1] + red[2] + red[3];
    float ts2 = red[4] + red[5] + red[6] + red[7];
    float mu  = ts * (1.f / Hc);
    float var = ts2 * (1.f / Hc) - mu * mu;
    float rs  = rsqrtf(var + 1e-5f);

#pragma unroll
    for (int i = 0; i < 8; i++) {
        int j = tid + i * 128;
        float res = 1.f / (1.f + expf(-res_gate[j]));
        Y[(size_t)m * Hc + j] = (v[i] - mu) * rs * gg[j] + bb[j]
                              + x[(size_t)m * Hc + j] * res;
    }
}

// ---------------------------------------------------------------------------
// Launch
// ---------------------------------------------------------------------------
extern "C" void kernel_launch(void* const* d_in, const int* in_sizes, int n_in,
                              void* d_out, int out_size) {
    (void)in_sizes; (void)n_in; (void)out_size;
    const float* x        = (const float*)d_in[0];
    const float* hx       = (const float*)d_in[1];
    const void*  is_init  = d_in[2];
    const float* W_ih     = (const float*)d_in[3];
    const float* W_hh     = (const float*)d_in[4];
    const float* b_ih     = (const float*)d_in[5];
    const float* b_hh     = (const float*)d_in[6];
    const float* ln_g     = (const float*)d_in[7];
    const float* ln_b     = (const float*)d_in[8];
    const float* res_gate = (const float*)d_in[9];

    float* Y    = (float*)d_out;
    float* Hseq = Y + (size_t)M1 * Hc;   // tuple order: (Y, Hseq)

    void *p_gi, *p_xhi, *p_xlo, *p_wihhi, *p_wihlo, *p_whhhi, *p_whhlo;
    cudaGetSymbolAddress(&p_gi,    g_gi);
    cudaGetSymbolAddress(&p_xhi,   g_x_hi);
    cudaGetSymbolAddress(&p_xlo,   g_x_lo);
    cudaGetSymbolAddress(&p_wihhi, g_wih_hi);
    cudaGetSymbolAddress(&p_wihlo, g_wih_lo);
    cudaGetSymbolAddress(&p_whhhi, g_whh_hi);
    cudaGetSymbolAddress(&p_whhlo, g_whh_lo);

    constexpr int SMEM_BIG  = 2 * (2 * 128 * 40 + 2 * 128 * 40) * 2;   // 81920
    constexpr int SMEM_PERS = 3 * (2 * 64 * 40 + 2 * 96 * 40) * 2;     // 76800
    cudaFuncSetAttribute(gemm_split<128, 128, 4, 2>,
                         cudaFuncAttributeMaxDynamicSharedMemorySize, SMEM_BIG);
    cudaFuncSetAttribute(gru_persistent,
                         cudaFuncAttributeMaxDynamicSharedMemorySize, SMEM_PERS);

    // 1) mask + barrier init
    detect_kernel<<<1, 256>>>((const unsigned char*)is_init);
    mask_kernel<<<(M1 + 255) / 256, 256>>>(is_init);
    bar_init_kernel<<<1, 32>>>();

    // 2) splits
    split_f32<<<8192, 256>>>(x,    (__nv_bfloat16*)p_xhi,   (__nv_bfloat16*)p_xlo,   (long)M1 * Dc);
    split_f32<<<2048, 256>>>(W_ih, (__nv_bfloat16*)p_wihhi, (__nv_bfloat16*)p_wihlo, (long)Gc * Dc);
    split_f32<<<2048, 256>>>(W_hh, (__nv_bfloat16*)p_whhhi, (__nv_bfloat16*)p_whhlo, (long)Gc * Hc);

    // 3) gi = x @ W_ih^T + b_ih
    gemm_split<128, 128, 4, 2><<<dim3(Gc / 128, M1 / 128), 256, SMEM_BIG>>>(
        (const __nv_bfloat16*)p_xhi,   (const __nv_bfloat16*)p_xlo,
        (const __nv_bfloat16*)p_wihhi, (const __nv_bfloat16*)p_wihlo,
        b_ih, (float*)p_gi, M1, Gc, Kc);

    // 4) h0
    init_h_kernel<<<(Bc * Hc + 255) / 256, 256>>>(hx);

    // 5) fused persistent recurrence (all 128 steps, one launch)
    gru_persistent<<<128, 256, SMEM_PERS>>>(
        (const float*)p_gi,
        (const __nv_bfloat16*)p_whhhi, (const __nv_bfloat16*)p_whhlo,
        b_hh, Hseq);

    // 6) Y
    ln_kernel<<<M1, 128>>>(Hseq, x, ln_g, ln_b, res_gate, Y);
}

// round 13
// speedup vs baseline: 1.0003x; 1.0003x over previous
#include <cuda_runtime.h>
#include <cuda_bf16.h>
#include <cstdint>
#include <cstddef>

// ---------------------------------------------------------------------------
// Problem constants
// ---------------------------------------------------------------------------
constexpr int Bc = 256;
constexpr int Tc = 128;
constexpr int Dc = 1024;
constexpr int Hc = 1024;
constexpr int Gc = 3 * Hc;        // 3072
constexpr int M1 = Bc * Tc;       // 32768
constexpr int Kc = 1024;

// ---------------------------------------------------------------------------
// Device scratch (static: no cudaMalloc allowed)
// ---------------------------------------------------------------------------
__device__ float         g_gi[(size_t)M1 * Gc];          // x @ W_ih^T + b_ih
__device__ __nv_bfloat16 g_h_hi[2][Bc * Hc];             // double-buffered masked h
__device__ __nv_bfloat16 g_h_lo[2][Bc * Hc];
__device__ __nv_bfloat16 g_x_hi[(size_t)M1 * Dc];
__device__ __nv_bfloat16 g_x_lo[(size_t)M1 * Dc];
__device__ __nv_bfloat16 g_wih_hi[(size_t)Gc * Dc];
__device__ __nv_bfloat16 g_wih_lo[(size_t)Gc * Dc];
__device__ __nv_bfloat16 g_whh_hi[(size_t)Gc * Hc];
__device__ __nv_bfloat16 g_whh_lo[(size_t)Gc * Hc];
__device__ float         g_mask[M1];                     // (~is_init) as float
__device__ int           g_mode;                         // 0=int32, 1=bool8, 2=float32
__device__ unsigned      g_epoch[4];                     // per-mi-group barrier epochs

// ---------------------------------------------------------------------------
// PTX helpers
// ---------------------------------------------------------------------------
__device__ __forceinline__ void cp16(uint32_t s, const void* g) {
    asm volatile("cp.async.cg.shared.global [%0], [%1], 16;" :: "r"(s), "l"(g));
}
__device__ __forceinline__ void ldsm4(uint32_t& r0, uint32_t& r1, uint32_t& r2, uint32_t& r3, uint32_t a) {
    asm volatile("ldmatrix.sync.aligned.m8n8.x4.shared.b16 {%0,%1,%2,%3}, [%4];"
                 : "=r"(r0), "=r"(r1), "=r"(r2), "=r"(r3) : "r"(a));
}
__device__ __forceinline__ void mma16816(float* c, const uint32_t* a, const uint32_t* b) {
    asm volatile("mma.sync.aligned.m16n8k16.row.col.f32.bf16.bf16.f32 "
                 "{%0,%1,%2,%3}, {%4,%5,%6,%7}, {%8,%9}, {%0,%1,%2,%3};"
                 : "+f"(c[0]), "+f"(c[1]), "+f"(c[2]), "+f"(c[3])
                 : "r"(a[0]), "r"(a[1]), "r"(a[2]), "r"(a[3]), "r"(b[0]), "r"(b[1]));
}

// ---------------------------------------------------------------------------
// Split-bf16 GEMM for gi:  C = (Ahi+Alo)[M,K] * (Bhi+Blo)[N,K]^T + bias
// (unchanged from R9/R11 passing kernel)
// ---------------------------------------------------------------------------
template<int BM, int BN, int WMS, int WNS>
__global__ void __launch_bounds__(WMS * WNS * 32)
gemm_split(const __nv_bfloat16* __restrict__ Ahi, const __nv_bfloat16* __restrict__ Alo,
           const __nv_bfloat16* __restrict__ Bhi, const __nv_bfloat16* __restrict__ Blo,
           const float* __restrict__ bias, float* __restrict__ C,
           int M, int N, int K)
{
    constexpr int NTHR  = WMS * WNS * 32;
    constexpr int WM    = BM / WMS;
    constexpr int WN    = BN / WNS;
    constexpr int MT    = WM / 16;
    constexpr int NT    = WN / 8;
    constexpr int LD    = 40;
    constexpr int TA    = BM * LD;
    constexpr int TB    = BN * LD;
    constexpr int STAGE = 2 * TA + 2 * TB;

    extern __shared__ __align__(16) __nv_bfloat16 smem[];

    const int tid  = threadIdx.x;
    const int lane = tid & 31;
    const int wid  = tid >> 5;
    const int wm   = wid / WNS;
    const int wn   = wid % WNS;
    const int tM   = blockIdx.y * BM;
    const int tN   = blockIdx.x * BN;
    const uint32_t sbase = (uint32_t)__cvta_generic_to_shared(smem);

    auto issue = [&](int kt, int st) {
        const int k0 = kt * 32;
        uint32_t aHi = sbase + (uint32_t)(st * STAGE) * 2u;
        uint32_t aLo = aHi + TA * 2;
        uint32_t bHi = aLo + TA * 2;
        uint32_t bLo = bHi + TB * 2;
        for (int c = tid; c < BM * 4; c += NTHR) {
            int r = c >> 2, q = c & 3;
            size_t go = (size_t)(tM + r) * K + k0 + q * 8;
            uint32_t so = (uint32_t)(r * LD + q * 8) * 2u;
            cp16(aHi + so, Ahi + go);
            cp16(aLo + so, Alo + go);
        }
        for (int c = tid; c < BN * 4; c += NTHR) {
            int r = c >> 2, q = c & 3;
            size_t go = (size_t)(tN + r) * K + k0 + q * 8;
            uint32_t so = (uint32_t)(r * LD + q * 8) * 2u;
            cp16(bHi + so, Bhi + go);
            cp16(bLo + so, Blo + go);
        }
        asm volatile("cp.async.commit_group;");
    };

    float acc[MT][NT][4];
#pragma unroll
    for (int i = 0; i < MT; i++)
#pragma unroll
        for (int j = 0; j < NT; j++)
#pragma unroll
            for (int k = 0; k < 4; k++) acc[i][j][k] = 0.f;

    const int NKT = K / 32;
    issue(0, 0);

    for (int kt = 0; kt < NKT; kt++) {
        const int st = kt & 1;
        if (kt + 1 < NKT) {
            issue(kt + 1, st ^ 1);
            asm volatile("cp.async.wait_group 1;");
        } else {
            asm volatile("cp.async.wait_group 0;");
        }
        __syncthreads();

        uint32_t aHi = sbase + (uint32_t)(st * STAGE) * 2u;
        uint32_t aLo = aHi + TA * 2;
        uint32_t bHi = aLo + TA * 2;
        uint32_t bLo = bHi + TB * 2;

#pragma unroll
        for (int kk = 0; kk < 32; kk += 16) {
            uint32_t ah[MT][4], al[MT][4];
#pragma unroll
            for (int mt = 0; mt < MT; mt++) {
                int row = wm * WM + mt * 16 + (lane & 7) + ((lane >> 3) & 1) * 8;
                int col = kk + (lane >> 4) * 8;
                uint32_t off = (uint32_t)(row * LD + col) * 2u;
                ldsm4(ah[mt][0], ah[mt][1], ah[mt][2], ah[mt][3], aHi + off);
                ldsm4(al[mt][0], al[mt][1], al[mt][2], al[mt][3], aLo + off);
            }
            uint32_t bh[NT][2], bl[NT][2];
#pragma unroll
            for (int p = 0; p < NT / 2; p++) {
                int nrow = wn * WN + p * 16 + ((lane >> 4) << 3) + (lane & 7);
                int kcol = kk + ((lane >> 3) & 1) * 8;
                uint32_t off = (uint32_t)(nrow * LD + kcol) * 2u;
                ldsm4(bh[2 * p][0], bh[2 * p][1], bh[2 * p + 1][0], bh[2 * p + 1][1], bHi + off);
                ldsm4(bl[2 * p][0], bl[2 * p][1], bl[2 * p + 1][0], bl[2 * p + 1][1], bLo + off);
            }
#pragma unroll
            for (int mt = 0; mt < MT; mt++)
#pragma unroll
                for (int nt = 0; nt < NT; nt++) {
                    mma16816(acc[mt][nt], ah[mt], bh[nt]);
                    mma16816(acc[mt][nt], ah[mt], bl[nt]);
                    mma16816(acc[mt][nt], al[mt], bh[nt]);
                }
        }
        __syncthreads();
    }

#pragma unroll
    for (int mt = 0; mt < MT; mt++) {
#pragma unroll
        for (int nt = 0; nt < NT; nt++) {
            int gr = tM + wm * WM + mt * 16 + (lane >> 2);
            int gc = tN + wn * WN + nt * 8 + (lane & 3) * 2;
            float b0 = bias[gc], b1 = bias[gc + 1];
            float2 v0 = make_float2(acc[mt][nt][0] + b0, acc[mt][nt][1] + b1);
            float2 v1 = make_float2(acc[mt][nt][2] + b0, acc[mt][nt][3] + b1);
            *reinterpret_cast<float2*>(C + (size_t)gr * N + gc)       = v0;
            *reinterpret_cast<float2*>(C + (size_t)(gr + 8) * N + gc) = v1;
        }
    }
}

// ---------------------------------------------------------------------------
// PERSISTENT fused recurrence kernel.
// Grid = 128 CTAs (<=148 SMs -> all co-resident; software barrier is safe).
// CTA (mi, ni): mi = blockIdx.x>>5 owns batch rows [64*mi, 64*mi+64);
//               ni = blockIdx.x&31 owns h-cols [32*ni, 32*ni+32).
// B-tile (96 rows) gathers W_hh rows {g*1024 + 32*ni + j : g in 0..2, j in 0..31}
// so r/z/n for each owned h-index are all inside this CTA -> fused pointwise
// epilogue. One epoch barrier per step per mi-group (groups are independent:
// batch rows never mix). h is double-buffered (bf16 hi/lo).
// ---------------------------------------------------------------------------
__global__ void __launch_bounds__(256, 1)
gru_persistent(const float* __restrict__ gi,
               const __nv_bfloat16* __restrict__ Whi,
               const __nv_bfloat16* __restrict__ Wlo,
               const float* __restrict__ b_hh,
               float* __restrict__ Hseq)
{
    constexpr int LD    = 40;
    constexpr int TA    = 64 * LD;             // 2560 elems
    constexpr int TB    = 96 * LD;             // 3840 elems
    constexpr int STAGE = 2 * TA + 2 * TB;     // 12800 elems per stage
    constexpr int NKT   = Kc / 32;             // 32
    constexpr int CLD   = 104;                 // fp32 C-tile row stride (8B-aligned float2)

    extern __shared__ __align__(16) __nv_bfloat16 smem[];
    float* Cs = reinterpret_cast<float*>(smem);   // reused after the k-loop

    const int tid  = threadIdx.x;
    const int lane = tid & 31;
    const int wid  = tid >> 5;
    const int wm   = wid >> 1;                 // 4 x 2 warps: WM=16, WN=48
    const int wn   = wid & 1;
    const int mi   = blockIdx.x >> 5;
    const int ni   = blockIdx.x & 31;
    const int m0   = mi * 64;
    const int j0   = ni * 32;
    const uint32_t sbase = (uint32_t)__cvta_generic_to_shared(smem);

    int buf = 0;
    for (int t = 0; t < Tc; t++) {
        const __nv_bfloat16* Ahi = g_h_hi[buf];
        const __nv_bfloat16* Alo = g_h_lo[buf];

        auto issue = [&](int kt, int st) {
            const int k0 = kt * 32;
            uint32_t aHi = sbase + (uint32_t)(st * STAGE) * 2u;
            uint32_t aLo = aHi + TA * 2;
            uint32_t bHi = aLo + TA * 2;
            uint32_t bLo = bHi + TB * 2;
            // A: 64 rows * 4 chunks = 256 tasks; B: 96 rows * 4 = 384 tasks
            for (int c = tid; c < 640; c += 256) {
                if (c < 256) {
                    int r = c >> 2, q = c & 3;
                    size_t go = (size_t)(m0 + r) * Kc + k0 + q * 8;
                    uint32_t so = (uint32_t)(r * LD + q * 8) * 2u;
                    cp16(aHi + so, Ahi + go);
                    cp16(aLo + so, Alo + go);
                } else {
                    int cc = c - 256;
                    int r = cc >> 2, q = cc & 3;       // r in [0,96)
                    int g = r >> 5, jj = r & 31;       // gate, h-offset
                    size_t go = (size_t)(g * Hc + j0 + jj) * Kc + k0 + q * 8;
                    uint32_t so = (uint32_t)(r * LD + q * 8) * 2u;
                    cp16(bHi + so, Whi + go);
                    cp16(bLo + so, Wlo + go);
                }
            }
            asm volatile("cp.async.commit_group;");
        };

        float acc[6][4];
#pragma unroll
        for (int j = 0; j < 6; j++)
#pragma unroll
            for (int k = 0; k < 4; k++) acc[j][k] = 0.f;

        issue(0, 0);
        issue(1, 1);

        for (int kt = 0; kt < NKT; kt++) {
            const int st = kt % 3;
            if (kt + 2 < NKT) {
                issue(kt + 2, (kt + 2) % 3);
                asm volatile("cp.async.wait_group 2;");
            } else if (kt + 1 < NKT) {
                asm volatile("cp.async.wait_group 1;");
            } else {
                asm volatile("cp.async.wait_group 0;");
            }
            __syncthreads();

            uint32_t aHi = sbase + (uint32_t)(st * STAGE) * 2u;
            uint32_t aLo = aHi + TA * 2;
            uint32_t bHi = aLo + TA * 2;
            uint32_t bLo = bHi + TB * 2;

#pragma unroll
            for (int kk = 0; kk < 32; kk += 16) {
                uint32_t ah[4], al[4];
                {
                    int row = wm * 16 + (lane & 7) + ((lane >> 3) & 1) * 8;
                    int col = kk + (lane >> 4) * 8;
                    uint32_t off = (uint32_t)(row * LD + col) * 2u;
                    ldsm4(ah[0], ah[1], ah[2], ah[3], aHi + off);
                    ldsm4(al[0], al[1], al[2], al[3], aLo + off);
                }
                uint32_t bh[6][2], bl[6][2];
#pragma unroll
                for (int p = 0; p < 3; p++) {
                    int nrow = wn * 48 + p * 16 + ((lane >> 4) << 3) + (lane & 7);
                    int kcol = kk + ((lane >> 3) & 1) * 8;
                    uint32_t off = (uint32_t)(nrow * LD + kcol) * 2u;
                    ldsm4(bh[2 * p][0], bh[2 * p][1], bh[2 * p + 1][0], bh[2 * p + 1][1], bHi + off);
                    ldsm4(bl[2 * p][0], bl[2 * p][1], bl[2 * p + 1][0], bl[2 * p + 1][1], bLo + off);
                }
#pragma unroll
                for (int nt = 0; nt < 6; nt++) {
                    mma16816(acc[nt], ah, bh[nt]);   // hi*hi
                    mma16816(acc[nt], ah, bl[nt]);   // hi*lo
                    mma16816(acc[nt], al, bh[nt]);   // lo*hi
                }
            }
            __syncthreads();
        }

        // ---- fused epilogue: acc -> smem C tile -> gates -> h update ----
#pragma unroll
        for (int nt = 0; nt < 6; nt++) {
            int rr = wm * 16 + (lane >> 2);
            int gc = wn * 48 + nt * 8 + (lane & 3) * 2;
            *reinterpret_cast<float2*>(&Cs[rr * CLD + gc])       = make_float2(acc[nt][0], acc[nt][1]);
            *reinterpret_cast<float2*>(&Cs[(rr + 8) * CLD + gc]) = make_float2(acc[nt][2], acc[nt][3]);
        }
        __syncthreads();

#pragma unroll
        for (int i = 0; i < 8; i++) {
            int e  = tid + i * 256;          // [0, 2048)
            int rr = e >> 5, jj = e & 31;
            int b  = m0 + rr, j = j0 + jj;

            size_t gib = ((size_t)b * Tc + t) * Gc + j;
            float ir  = gi[gib];
            float iz  = gi[gib + Hc];
            float inn = gi[gib + 2 * Hc];

            float hr = Cs[rr * CLD + jj]      + b_hh[j];
            float hz = Cs[rr * CLD + 32 + jj] + b_hh[Hc + j];
            float hn = Cs[rr * CLD + 64 + jj] + b_hh[2 * Hc + j];

            size_t hidx = (size_t)b * Hc + j;
            float h = __bfloat162float(g_h_hi[buf][hidx]) + __bfloat162float(g_h_lo[buf][hidx]);

            float r = 1.f / (1.f + expf(-(ir + hr)));
            float z = 1.f / (1.f + expf(-(iz + hz)));
            float n = tanhf(inn + r * hn);
            float hnew = (1.f - z) * n + z * h;

            Hseq[((size_t)b * Tc + t) * Hc + j] = hnew;

            float m  = (t + 1 < Tc) ? g_mask[b * Tc + t + 1] : 0.f;
            float hm = hnew * m;
            __nv_bfloat16 hh = __float2bfloat16(hm);
            g_h_hi[buf ^ 1][hidx] = hh;
            g_h_lo[buf ^ 1][hidx] = __float2bfloat16(hm - __bfloat162float(hh));
        }

        // ---- per-group grid barrier (32 CTAs share batch rows of mi) ----
        if (t + 1 < Tc) {
            __syncthreads();
            if (tid == 0) {
                __threadfence();                       // publish h writes
                atomicAdd(&g_epoch[mi], 1u);
                unsigned want = 32u * (unsigned)(t + 1);
                while (atomicAdd(&g_epoch[mi], 0u) < want) __nanosleep(64);
                __threadfence();                       // acquire peers' h writes
            }
            __syncthreads();
        }
        buf ^= 1;
    }
}

// ---------------------------------------------------------------------------
// Mask dtype detection (is_init may be bool8 / int32 / float32)
// ---------------------------------------------------------------------------
__global__ void detect_kernel(const unsigned char* __restrict__ p) {
    __shared__ int nz_off, f3;
    if (threadIdx.x == 0) { nz_off = 0; f3 = 0; }
    __syncthreads();
    int local_nz = 0, local_f3 = 0;
    for (int i = threadIdx.x; i < M1; i += blockDim.x) {
        unsigned char c = p[i];
        if ((i & 3) != 0 && c) local_nz = 1;
        if ((i & 3) == 3 && c == 0x3F) local_f3 = 1;
    }
    if (local_nz) atomicOr(&nz_off, 1);
    if (local_f3) atomicOr(&f3, 1);
    __syncthreads();
    if (threadIdx.x == 0) g_mode = (!nz_off) ? 0 : (f3 ? 2 : 1);
}

__global__ void mask_kernel(const void* __restrict__ p) {
    int i = blockIdx.x * blockDim.x + threadIdx.x;
    if (i >= M1) return;
    int mode = g_mode;
    int v;
    if (mode == 0)      v = (((const int*)p)[i] != 0);
    else if (mode == 1) v = (((const unsigned char*)p)[i] != 0);
    else                v = (((const float*)p)[i] != 0.f);
    g_mask[i] = v ? 0.f : 1.f;
}

__global__ void bar_init_kernel() {
    if (threadIdx.x < 4) g_epoch[threadIdx.x] = 0u;
}

// ---------------------------------------------------------------------------
// fp32 -> (bf16 hi, bf16 lo) split
// ---------------------------------------------------------------------------
__global__ void split_f32(const float* __restrict__ src,
                          __nv_bfloat16* __restrict__ hi, __nv_bfloat16* __restrict__ lo,
                          long n) {
    long stride = (long)gridDim.x * blockDim.x;
    for (long i = (long)blockIdx.x * blockDim.x + threadIdx.x; i < n; i += stride) {
        float v = src[i];
        __nv_bfloat16 h = __float2bfloat16(v);
        hi[i] = h;
        lo[i] = __float2bfloat16(v - __bfloat162float(h));
    }
}

// ---------------------------------------------------------------------------
// h0 = hx * mask[:,0] -> buffer 0 (bf16 hi/lo)
// ---------------------------------------------------------------------------
__global__ void init_h_kernel(const float* __restrict__ hx) {
    int idx = blockIdx.x * blockDim.x + threadIdx.x;
    if (idx >= Bc * Hc) return;
    int b = idx >> 10;
    float v = hx[idx] * g_mask[(size_t)b * Tc + 0];
    __nv_bfloat16 h = __float2bfloat16(v);
    g_h_hi[0][idx] = h;
    g_h_lo[0][idx] = __float2bfloat16(v - __bfloat162float(h));
}

// ---------------------------------------------------------------------------
// Y = LN(Hseq)*g + b + x*sigmoid(res_gate)
// ---------------------------------------------------------------------------
__global__ void ln_kernel(const float* __restrict__ Hseq, const float* __restrict__ x,
                          const float* __restrict__ gg, const float* __restrict__ bb,
                          const float* __restrict__ res_gate, float* __restrict__ Y) {
    int m = blockIdx.x;
    const float* row = Hseq + (size_t)m * Hc;
    int tid = threadIdx.x;
    int lane = tid & 31, wid = tid >> 5;

    float v[8];
    float s = 0.f, s2 = 0.f;
#pragma unroll
    for (int i = 0; i < 8; i++) {
        float t = row[tid + i * 128];
        v[i] = t; s += t; s2 += t * t;
    }
#pragma unroll
    for (int o = 16; o; o >>= 1) {
        s  += __shfl_xor_sync(0xffffffffu, s, o);
        s2 += __shfl_xor_sync(0xffffffffu, s2, o);
    }
    __shared__ float red[8];
    if (lane == 0) { red[wid] = s; red[4 + wid] = s2; }
    __syncthreads();
    float ts  = red[0] + red[1] + red[2] + red[3];
    float ts2 = red[4] + red[5] + red[6] + red[7];
    float mu  = ts * (1.f / Hc);
    float var = ts2 * (1.f / Hc) - mu * mu;
    float rs  = rsqrtf(var + 1e-5f);

#pragma unroll
    for (int i = 0; i < 8; i++) {
        int j = tid + i * 128;
        float res = 1.f / (1.f + expf(-res_gate[j]));
        Y[(size_t)m * Hc + j] = (v[i] - mu) * rs * gg[j] + bb[j]
                              + x[(size_t)m * Hc + j] * res;
    }
}

// ---------------------------------------------------------------------------
// Launch
// ---------------------------------------------------------------------------
extern "C" void kernel_launch(void* const* d_in, const int* in_sizes, int n_in,
                              void* d_out, int out_size) {
    (void)in_sizes; (void)n_in; (void)out_size;
    const float* x        = (const float*)d_in[0];
    const float* hx       = (const float*)d_in[1];
    const void*  is_init  = d_in[2];
    const float* W_ih     = (const float*)d_in[3];
    const float* W_hh     = (const float*)d_in[4];
    const float* b_ih     = (const float*)d_in[5];
    const float* b_hh     = (const float*)d_in[6];
    const float* ln_g     = (const float*)d_in[7];
    const float* ln_b     = (const float*)d_in[8];
    const float* res_gate = (const float*)d_in[9];

    float* Y    = (float*)d_out;
    float* Hseq = Y + (size_t)M1 * Hc;   // tuple order: (Y, Hseq)

    void *p_gi, *p_xhi, *p_xlo, *p_wihhi, *p_wihlo, *p_whhhi, *p_whhlo;
    cudaGetSymbolAddress(&p_gi,    g_gi);
    cudaGetSymbolAddress(&p_xhi,   g_x_hi);
    cudaGetSymbolAddress(&p_xlo,   g_x_lo);
    cudaGetSymbolAddress(&p_wihhi, g_wih_hi);
    cudaGetSymbolAddress(&p_wihlo, g_wih_lo);
    cudaGetSymbolAddress(&p_whhhi, g_whh_hi);
    cudaGetSymbolAddress(&p_whhlo, g_whh_lo);

    constexpr int SMEM_BIG  = 2 * (2 * 128 * 40 + 2 * 128 * 40) * 2;   // 81920
    constexpr int SMEM_PERS = 3 * (2 * 64 * 40 + 2 * 96 * 40) * 2;     // 76800
    cudaFuncSetAttribute(gemm_split<128, 128, 4, 2>,
                         cudaFuncAttributeMaxDynamicSharedMemorySize, SMEM_BIG);
    cudaFuncSetAttribute(gru_persistent,
                         cudaFuncAttributeMaxDynamicSharedMemorySize, SMEM_PERS);

    // 1) mask + barrier init
    detect_kernel<<<1, 256>>>((const unsigned char*)is_init);
    mask_kernel<<<(M1 + 255) / 256, 256>>>(is_init);
    bar_init_kernel<<<1, 32>>>();

    // 2) splits
    split_f32<<<8192, 256>>>(x,    (__nv_bfloat16*)p_xhi,   (__nv_bfloat16*)p_xlo,   (long)M1 * Dc);
    split_f32<<<2048, 256>>>(W_ih, (__nv_bfloat16*)p_wihhi, (__nv_bfloat16*)p_wihlo, (long)Gc * Dc);
    split_f32<<<2048, 256>>>(W_hh, (__nv_bfloat16*)p_whhhi, (__nv_bfloat16*)p_whhlo, (long)Gc * Hc);

    // 3) gi = x @ W_ih^T + b_ih
    gemm_split<128, 128, 4, 2><<<dim3(Gc / 128, M1 / 128), 256, SMEM_BIG>>>(
        (const __nv_bfloat16*)p_xhi,   (const __nv_bfloat16*)p_xlo,
        (const __nv_bfloat16*)p_wihhi, (const __nv_bfloat16*)p_wihlo,
        b_ih, (float*)p_gi, M1, Gc, Kc);

    // 4) h0
    init_h_kernel<<<(Bc * Hc + 255) / 256, 256>>>(hx);

    // 5) fused persistent recurrence (all 128 steps, one launch)
    gru_persistent<<<128, 256, SMEM_PERS>>>(
        (const float*)p_gi,
        (const __nv_bfloat16*)p_whhhi, (const __nv_bfloat16*)p_whhlo,
        b_hh, Hseq);

    // 6) Y
    ln_kernel<<<M1, 128>>>(Hseq, x, ln_g, ln_b, res_gate, Y);
}

// round 14
// speedup vs baseline: 1.0969x; 1.0965x over previous
#include <cuda_runtime.h>
#include <cuda_bf16.h>
#include <cstdint>
#include <cstddef>

// ---------------------------------------------------------------------------
// Problem constants
// ---------------------------------------------------------------------------
constexpr int Bc = 256;
constexpr int Tc = 128;
constexpr int Dc = 1024;
constexpr int Hc = 1024;
constexpr int Gc = 3 * Hc;        // 3072
constexpr int M1 = Bc * Tc;       // 32768
constexpr int Kc = 1024;

// ---------------------------------------------------------------------------
// Device scratch (static: no cudaMalloc allowed)
// ---------------------------------------------------------------------------
__device__ float         g_gi[(size_t)M1 * Gc];          // x @ W_ih^T + b_ih
__device__ __nv_bfloat16 g_h_hi[2][Bc * Hc];             // double-buffered masked h
__device__ __nv_bfloat16 g_h_lo[2][Bc * Hc];
__device__ __nv_bfloat16 g_x_hi[(size_t)M1 * Dc];
__device__ __nv_bfloat16 g_x_lo[(size_t)M1 * Dc];
__device__ __nv_bfloat16 g_wih_hi[(size_t)Gc * Dc];
__device__ __nv_bfloat16 g_wih_lo[(size_t)Gc * Dc];
__device__ __nv_bfloat16 g_whh_hi[(size_t)Gc * Hc];
__device__ __nv_bfloat16 g_whh_lo[(size_t)Gc * Hc];
__device__ float         g_mask[M1];                     // (~is_init) as float
__device__ int           g_mode;                         // 0=int32, 1=bool8, 2=float32

// ---------------------------------------------------------------------------
// PTX helpers
// ---------------------------------------------------------------------------
__device__ __forceinline__ void cp16(uint32_t s, const void* g) {
    asm volatile("cp.async.cg.shared.global [%0], [%1], 16;" :: "r"(s), "l"(g));
}
__device__ __forceinline__ void ldsm4(uint32_t& r0, uint32_t& r1, uint32_t& r2, uint32_t& r3, uint32_t a) {
    asm volatile("ldmatrix.sync.aligned.m8n8.x4.shared.b16 {%0,%1,%2,%3}, [%4];"
                 : "=r"(r0), "=r"(r1), "=r"(r2), "=r"(r3) : "r"(a));
}
__device__ __forceinline__ void mma16816(float* c, const uint32_t* a, const uint32_t* b) {
    asm volatile("mma.sync.aligned.m16n8k16.row.col.f32.bf16.bf16.f32 "
                 "{%0,%1,%2,%3}, {%4,%5,%6,%7}, {%8,%9}, {%0,%1,%2,%3};"
                 : "+f"(c[0]), "+f"(c[1]), "+f"(c[2]), "+f"(c[3])
                 : "r"(a[0]), "r"(a[1]), "r"(a[2]), "r"(a[3]), "r"(b[0]), "r"(b[1]));
}

// ---------------------------------------------------------------------------
// Split-bf16 GEMM for gi:  C = (Ahi+Alo)[M,K] * (Bhi+Blo)[N,K]^T + bias
// 3-stage cp.async pipeline (was 2-stage in R11/R13).
// ---------------------------------------------------------------------------
template<int BM, int BN, int WMS, int WNS>
__global__ void __launch_bounds__(WMS * WNS * 32)
gemm_split(const __nv_bfloat16* __restrict__ Ahi, const __nv_bfloat16* __restrict__ Alo,
           const __nv_bfloat16* __restrict__ Bhi, const __nv_bfloat16* __restrict__ Blo,
           const float* __restrict__ bias, float* __restrict__ C,
           int M, int N, int K)
{
    constexpr int NTHR  = WMS * WNS * 32;
    constexpr int WM    = BM / WMS;
    constexpr int WN    = BN / WNS;
    constexpr int MT    = WM / 16;
    constexpr int NT    = WN / 8;
    constexpr int LD    = 40;
    constexpr int TA    = BM * LD;
    constexpr int TB    = BN * LD;
    constexpr int STAGE = 2 * TA + 2 * TB;

    extern __shared__ __align__(16) __nv_bfloat16 smem[];

    const int tid  = threadIdx.x;
    const int lane = tid & 31;
    const int wid  = tid >> 5;
    const int wm   = wid / WNS;
    const int wn   = wid % WNS;
    const int tM   = blockIdx.y * BM;
    const int tN   = blockIdx.x * BN;
    const uint32_t sbase = (uint32_t)__cvta_generic_to_shared(smem);

    auto issue = [&](int kt, int st) {
        const int k0 = kt * 32;
        uint32_t aHi = sbase + (uint32_t)(st * STAGE) * 2u;
        uint32_t aLo = aHi + TA * 2;
        uint32_t bHi = aLo + TA * 2;
        uint32_t bLo = bHi + TB * 2;
        for (int c = tid; c < BM * 4; c += NTHR) {
            int r = c >> 2, q = c & 3;
            size_t go = (size_t)(tM + r) * K + k0 + q * 8;
            uint32_t so = (uint32_t)(r * LD + q * 8) * 2u;
            cp16(aHi + so, Ahi + go);
            cp16(aLo + so, Alo + go);
        }
        for (int c = tid; c < BN * 4; c += NTHR) {
            int r = c >> 2, q = c & 3;
            size_t go = (size_t)(tN + r) * K + k0 + q * 8;
            uint32_t so = (uint32_t)(r * LD + q * 8) * 2u;
            cp16(bHi + so, Bhi + go);
            cp16(bLo + so, Blo + go);
        }
        asm volatile("cp.async.commit_group;");
    };

    float acc[MT][NT][4];
#pragma unroll
    for (int i = 0; i < MT; i++)
#pragma unroll
        for (int j = 0; j < NT; j++)
#pragma unroll
            for (int k = 0; k < 4; k++) acc[i][j][k] = 0.f;

    const int NKT = K / 32;
    issue(0, 0);
    issue(1, 1);

    for (int kt = 0; kt < NKT; kt++) {
        const int st = kt % 3;
        if (kt + 2 < NKT) {
            issue(kt + 2, (kt + 2) % 3);
            asm volatile("cp.async.wait_group 2;");
        } else if (kt + 1 < NKT) {
            asm volatile("cp.async.wait_group 1;");
        } else {
            asm volatile("cp.async.wait_group 0;");
        }
        __syncthreads();

        uint32_t aHi = sbase + (uint32_t)(st * STAGE) * 2u;
        uint32_t aLo = aHi + TA * 2;
        uint32_t bHi = aLo + TA * 2;
        uint32_t bLo = bHi + TB * 2;

#pragma unroll
        for (int kk = 0; kk < 32; kk += 16) {
            uint32_t ah[MT][4], al[MT][4];
#pragma unroll
            for (int mt = 0; mt < MT; mt++) {
                int row = wm * WM + mt * 16 + (lane & 7) + ((lane >> 3) & 1) * 8;
                int col = kk + (lane >> 4) * 8;
                uint32_t off = (uint32_t)(row * LD + col) * 2u;
                ldsm4(ah[mt][0], ah[mt][1], ah[mt][2], ah[mt][3], aHi + off);
                ldsm4(al[mt][0], al[mt][1], al[mt][2], al[mt][3], aLo + off);
            }
            uint32_t bh[NT][2], bl[NT][2];
#pragma unroll
            for (int p = 0; p < NT / 2; p++) {
                int nrow = wn * WN + p * 16 + ((lane >> 4) << 3) + (lane & 7);
                int kcol = kk + ((lane >> 3) & 1) * 8;
                uint32_t off = (uint32_t)(nrow * LD + kcol) * 2u;
                ldsm4(bh[2 * p][0], bh[2 * p][1], bh[2 * p + 1][0], bh[2 * p + 1][1], bHi + off);
                ldsm4(bl[2 * p][0], bl[2 * p][1], bl[2 * p + 1][0], bl[2 * p + 1][1], bLo + off);
            }
#pragma unroll
            for (int mt = 0; mt < MT; mt++)
#pragma unroll
                for (int nt = 0; nt < NT; nt++) {
                    mma16816(acc[mt][nt], ah[mt], bh[nt]);
                    mma16816(acc[mt][nt], ah[mt], bl[nt]);
                    mma16816(acc[mt][nt], al[mt], bh[nt]);
                }
        }
        __syncthreads();
    }

#pragma unroll
    for (int mt = 0; mt < MT; mt++) {
#pragma unroll
        for (int nt = 0; nt < NT; nt++) {
            int gr = tM + wm * WM + mt * 16 + (lane >> 2);
            int gc = tN + wn * WN + nt * 8 + (lane & 3) * 2;
            float b0 = bias[gc], b1 = bias[gc + 1];
            float2 v0 = make_float2(acc[mt][nt][0] + b0, acc[mt][nt][1] + b1);
            float2 v1 = make_float2(acc[mt][nt][2] + b0, acc[mt][nt][3] + b1);
            *reinterpret_cast<float2*>(C + (size_t)gr * N + gc)       = v0;
            *reinterpret_cast<float2*>(C + (size_t)(gr + 8) * N + gc) = v1;
        }
    }
}

// ---------------------------------------------------------------------------
// Fused GRU step (ONE launch per t; kernel boundary = cross-CTA sync).
// Grid = 128 CTAs. CTA (mi = blockIdx.x>>5, ni = blockIdx.x&31):
//   batch rows [64*mi, 64*mi+64), h-cols [32*ni, 32*ni+32).
// B-tile (96 rows) gathers W_hh rows {g*1024 + 32*ni + j} -> all 3 gates for
// each owned h-index live in this CTA -> pointwise fused in epilogue.
// gi and h preloaded into registers before the k-loop (overlap with GEMM).
// h double-buffered: read buf = t&1, write buf^1.
// ---------------------------------------------------------------------------
__global__ void __launch_bounds__(256, 1)
gru_step(const float* __restrict__ gi,
         const __nv_bfloat16* __restrict__ Whi,
         const __nv_bfloat16* __restrict__ Wlo,
         const float* __restrict__ b_hh,
         float* __restrict__ Hseq, int t)
{
    constexpr int LD    = 40;
    constexpr int TA    = 64 * LD;             // 2560 elems
    constexpr int TB    = 96 * LD;             // 3840 elems
    constexpr int STAGE = 2 * TA + 2 * TB;     // 12800 elems per stage
    constexpr int NKT   = Kc / 32;             // 32
    constexpr int CLD   = 104;                 // fp32 C-tile row stride

    extern __shared__ __align__(16) __nv_bfloat16 smem[];
    float* Cs = reinterpret_cast<float*>(smem);   // reused after the k-loop

    const int tid  = threadIdx.x;
    const int lane = tid & 31;
    const int wid  = tid >> 5;
    const int wm   = wid >> 1;                 // 4 x 2 warps: WM=16, WN=48
    const int wn   = wid & 1;
    const int mi   = blockIdx.x >> 5;
    const int ni   = blockIdx.x & 31;
    const int m0   = mi * 64;
    const int j0   = ni * 32;
    const int buf  = t & 1;
    const uint32_t sbase = (uint32_t)__cvta_generic_to_shared(smem);

    const __nv_bfloat16* Ahi = g_h_hi[buf];
    const __nv_bfloat16* Alo = g_h_lo[buf];

    auto issue = [&](int kt, int st) {
        const int k0 = kt * 32;
        uint32_t aHi = sbase + (uint32_t)(st * STAGE) * 2u;
        uint32_t aLo = aHi + TA * 2;
        uint32_t bHi = aLo + TA * 2;
        uint32_t bLo = bHi + TB * 2;
        for (int c = tid; c < 640; c += 256) {
            if (c < 256) {
                int r = c >> 2, q = c & 3;
                size_t go = (size_t)(m0 + r) * Kc + k0 + q * 8;
                uint32_t so = (uint32_t)(r * LD + q * 8) * 2u;
                cp16(aHi + so, Ahi + go);
                cp16(aLo + so, Alo + go);
            } else {
                int cc = c - 256;
                int r = cc >> 2, q = cc & 3;       // r in [0,96)
                int g = r >> 5, jj = r & 31;
                size_t go = (size_t)(g * Hc + j0 + jj) * Kc + k0 + q * 8;
                uint32_t so = (uint32_t)(r * LD + q * 8) * 2u;
                cp16(bHi + so, Whi + go);
                cp16(bLo + so, Wlo + go);
            }
        }
        asm volatile("cp.async.commit_group;");
    };

    float acc[6][4];
#pragma unroll
    for (int j = 0; j < 6; j++)
#pragma unroll
        for (int k = 0; k < 4; k++) acc[j][k] = 0.f;

    issue(0, 0);
    issue(1, 1);

    // ---- preload gi + h for this thread's epilogue lanes (overlaps GEMM) ----
    float p_ir[8], p_iz[8], p_in[8], p_h[8];
#pragma unroll
    for (int i = 0; i < 8; i++) {
        int e  = tid + i * 256;
        int rr = e >> 5, jj = e & 31;
        int b  = m0 + rr, j = j0 + jj;
        size_t gib = ((size_t)b * Tc + t) * Gc + j;
        p_ir[i] = gi[gib];
        p_iz[i] = gi[gib + Hc];
        p_in[i] = gi[gib + 2 * Hc];
        size_t hidx = (size_t)b * Hc + j;
        p_h[i] = __bfloat162float(Ahi[hidx]) + __bfloat162float(Alo[hidx]);
    }

    for (int kt = 0; kt < NKT; kt++) {
        const int st = kt % 3;
        if (kt + 2 < NKT) {
            issue(kt + 2, (kt + 2) % 3);
            asm volatile("cp.async.wait_group 2;");
        } else if (kt + 1 < NKT) {
            asm volatile("cp.async.wait_group 1;");
        } else {
            asm volatile("cp.async.wait_group 0;");
        }
        __syncthreads();

        uint32_t aHi = sbase + (uint32_t)(st * STAGE) * 2u;
        uint32_t aLo = aHi + TA * 2;
        uint32_t bHi = aLo + TA * 2;
        uint32_t bLo = bHi + TB * 2;

#pragma unroll
        for (int kk = 0; kk < 32; kk += 16) {
            uint32_t ah[4], al[4];
            {
                int row = wm * 16 + (lane & 7) + ((lane >> 3) & 1) * 8;
                int col = kk + (lane >> 4) * 8;
                uint32_t off = (uint32_t)(row * LD + col) * 2u;
                ldsm4(ah[0], ah[1], ah[2], ah[3], aHi + off);
                ldsm4(al[0], al[1], al[2], al[3], aLo + off);
            }
            uint32_t bh[6][2], bl[6][2];
#pragma unroll
            for (int p = 0; p < 3; p++) {
                int nrow = wn * 48 + p * 16 + ((lane >> 4) << 3) + (lane & 7);
                int kcol = kk + ((lane >> 3) & 1) * 8;
                uint32_t off = (uint32_t)(nrow * LD + kcol) * 2u;
                ldsm4(bh[2 * p][0], bh[2 * p][1], bh[2 * p + 1][0], bh[2 * p + 1][1], bHi + off);
                ldsm4(bl[2 * p][0], bl[2 * p][1], bl[2 * p + 1][0], bl[2 * p + 1][1], bLo + off);
            }
#pragma unroll
            for (int nt = 0; nt < 6; nt++) {
                mma16816(acc[nt], ah, bh[nt]);   // hi*hi
                mma16816(acc[nt], ah, bl[nt]);   // hi*lo
                mma16816(acc[nt], al, bh[nt]);   // lo*hi
            }
        }
        __syncthreads();
    }

    // ---- fused epilogue: acc -> smem C tile -> gates -> h update ----
#pragma unroll
    for (int nt = 0; nt < 6; nt++) {
        int rr = wm * 16 + (lane >> 2);
        int gc = wn * 48 + nt * 8 + (lane & 3) * 2;
        *reinterpret_cast<float2*>(&Cs[rr * CLD + gc])       = make_float2(acc[nt][0], acc[nt][1]);
        *reinterpret_cast<float2*>(&Cs[(rr + 8) * CLD + gc]) = make_float2(acc[nt][2], acc[nt][3]);
    }
    __syncthreads();

#pragma unroll
    for (int i = 0; i < 8; i++) {
        int e  = tid + i * 256;
        int rr = e >> 5, jj = e & 31;
        int b  = m0 + rr, j = j0 + jj;

        float hr = Cs[rr * CLD + jj]      + b_hh[j];
        float hz = Cs[rr * CLD + 32 + jj] + b_hh[Hc + j];
        float hn = Cs[rr * CLD + 64 + jj] + b_hh[2 * Hc + j];

        float h = p_h[i];
        float r = 1.f / (1.f + expf(-(p_ir[i] + hr)));
        float z = 1.f / (1.f + expf(-(p_iz[i] + hz)));
        float n = tanhf(p_in[i] + r * hn);
        float hnew = (1.f - z) * n + z * h;

        Hseq[((size_t)b * Tc + t) * Hc + j] = hnew;

        float m  = (t + 1 < Tc) ? g_mask[b * Tc + t + 1] : 0.f;
        float hm = hnew * m;
        size_t hidx = (size_t)b * Hc + j;
        __nv_bfloat16 hh = __float2bfloat16(hm);
        g_h_hi[buf ^ 1][hidx] = hh;
        g_h_lo[buf ^ 1][hidx] = __float2bfloat16(hm - __bfloat162float(hh));
    }
}

// ---------------------------------------------------------------------------
// Mask dtype detection (is_init may be bool8 / int32 / float32)
// ---------------------------------------------------------------------------
__global__ void detect_kernel(const unsigned char* __restrict__ p) {
    __shared__ int nz_off, f3;
    if (threadIdx.x == 0) { nz_off = 0; f3 = 0; }
    __syncthreads();
    int local_nz = 0, local_f3 = 0;
    for (int i = threadIdx.x; i < M1; i += blockDim.x) {
        unsigned char c = p[i];
        if ((i & 3) != 0 && c) local_nz = 1;
        if ((i & 3) == 3 && c == 0x3F) local_f3 = 1;
    }
    if (local_nz) atomicOr(&nz_off, 1);
    if (local_f3) atomicOr(&f3, 1);
    __syncthreads();
    if (threadIdx.x == 0) g_mode = (!nz_off) ? 0 : (f3 ? 2 : 1);
}

__global__ void mask_kernel(const void* __restrict__ p) {
    int i = blockIdx.x * blockDim.x + threadIdx.x;
    if (i >= M1) return;
    int mode = g_mode;
    int v;
    if (mode == 0)      v = (((const int*)p)[i] != 0);
    else if (mode == 1) v = (((const unsigned char*)p)[i] != 0);
    else                v = (((const float*)p)[i] != 0.f);
    g_mask[i] = v ? 0.f : 1.f;
}

// ---------------------------------------------------------------------------
// Fused fp32 -> (bf16 hi, lo) split for x, W_ih, W_hh (one launch).
// ---------------------------------------------------------------------------
__device__ __forceinline__ void split_range(const float* __restrict__ src,
                                            __nv_bfloat16* __restrict__ hi,
                                            __nv_bfloat16* __restrict__ lo,
                                            long n, long tid0, long stride) {
    for (long i = tid0; i < n; i += stride) {
        float v = src[i];
        __nv_bfloat16 h = __float2bfloat16(v);
        hi[i] = h;
        lo[i] = __float2bfloat16(v - __bfloat162float(h));
    }
}

__global__ void split_all(const float* __restrict__ x,
                          const float* __restrict__ wih,
                          const float* __restrict__ whh) {
    long tid0   = (long)blockIdx.x * blockDim.x + threadIdx.x;
    long stride = (long)gridDim.x * blockDim.x;
    split_range(x,   g_x_hi,   g_x_lo,   (long)M1 * Dc, tid0, stride);
    split_range(wih, g_wih_hi, g_wih_lo, (long)Gc * Dc, tid0, stride);
    split_range(whh, g_whh_hi, g_whh_lo, (long)Gc * Hc, tid0, stride);
}

// ---------------------------------------------------------------------------
// h0 = hx * mask[:,0] -> buffer 0 (bf16 hi/lo)
// ---------------------------------------------------------------------------
__global__ void init_h_kernel(const float* __restrict__ hx) {
    int idx = blockIdx.x * blockDim.x + threadIdx.x;
    if (idx >= Bc * Hc) return;
    int b = idx >> 10;
    float v = hx[idx] * g_mask[(size_t)b * Tc + 0];
    __nv_bfloat16 h = __float2bfloat16(v);
    g_h_hi[0][idx] = h;
    g_h_lo[0][idx] = __float2bfloat16(v - __bfloat162float(h));
}

// ---------------------------------------------------------------------------
// Y = LN(Hseq)*g + b + x*sigmoid(res_gate)
// ---------------------------------------------------------------------------
__global__ void ln_kernel(const float* __restrict__ Hseq, const float* __restrict__ x,
                          const float* __restrict__ gg, const float* __restrict__ bb,
                          const float* __restrict__ res_gate, float* __restrict__ Y) {
    int m = blockIdx.x;
    const float* row = Hseq + (size_t)m * Hc;
    int tid = threadIdx.x;
    int lane = tid & 31, wid = tid >> 5;

    float v[8];
    float s = 0.f, s2 = 0.f;
#pragma unroll
    for (int i = 0; i < 8; i++) {
        float t = row[tid + i * 128];
        v[i] = t; s += t; s2 += t * t;
    }
#pragma unroll
    for (int o = 16; o; o >>= 1) {
        s  += __shfl_xor_sync(0xffffffffu, s, o);
        s2 += __shfl_xor_sync(0xffffffffu, s2, o);
    }
    __shared__ float red[8];
    if (lane == 0) { red[wid] = s; red[4 + wid] = s2; }
    __syncthreads();
    float ts  = red[0] + red[1] + red[2] + red[3];
    float ts2 = red[4] + red[5] + red[6] + red[7];
    float mu  = ts * (1.f / Hc);
    float var = ts2 * (1.f / Hc) - mu * mu;
    float rs  = rsqrtf(var + 1e-5f);

#pragma unroll
    for (int i = 0; i < 8; i++) {
        int j = tid + i * 128;
        float res = 1.f / (1.f + expf(-res_gate[j]));
        Y[(size_t)m * Hc + j] = (v[i] - mu) * rs * gg[j] + bb[j]
                              + x[(size_t)m * Hc + j] * res;
    }
}

// ---------------------------------------------------------------------------
// Launch
// ---------------------------------------------------------------------------
extern "C" void kernel_launch(void* const* d_in, const int* in_sizes, int n_in,
                              void* d_out, int out_size) {
    (void)in_sizes; (void)n_in; (void)out_size;
    const float* x        = (const float*)d_in[0];
    const float* hx       = (const float*)d_in[1];
    const void*  is_init  = d_in[2];
    const float* W_ih     = (const float*)d_in[3];
    const float* W_hh     = (const float*)d_in[4];
    const float* b_ih     = (const float*)d_in[5];
    const float* b_hh     = (const float*)d_in[6];
    const float* ln_g     = (const float*)d_in[7];
    const float* ln_b     = (const float*)d_in[8];
    const float* res_gate = (const float*)d_in[9];

    float* Y    = (float*)d_out;
    float* Hseq = Y + (size_t)M1 * Hc;   // tuple order: (Y, Hseq)

    void *p_gi, *p_xhi, *p_xlo, *p_wihhi, *p_wihlo, *p_whhhi, *p_whhlo;
    cudaGetSymbolAddress(&p_gi,    g_gi);
    cudaGetSymbolAddress(&p_xhi,   g_x_hi);
    cudaGetSymbolAddress(&p_xlo,   g_x_lo);
    cudaGetSymbolAddress(&p_wihhi, g_wih_hi);
    cudaGetSymbolAddress(&p_wihlo, g_wih_lo);
    cudaGetSymbolAddress(&p_whhhi, g_whh_hi);
    cudaGetSymbolAddress(&p_whhlo, g_whh_lo);

    constexpr int SMEM_BIG  = 3 * (2 * 128 * 40 + 2 * 128 * 40) * 2;   // 122880 (3-stage)
    constexpr int SMEM_STEP = 3 * (2 * 64 * 40 + 2 * 96 * 40) * 2;     // 76800
    cudaFuncSetAttribute(gemm_split<128, 128, 4, 2>,
                         cudaFuncAttributeMaxDynamicSharedMemorySize, SMEM_BIG);
    cudaFuncSetAttribute(gru_step,
                         cudaFuncAttributeMaxDynamicSharedMemorySize, SMEM_STEP);

    // Launch order matters for ncu sampling: gi GEMM is the 4th launch.
    detect_kernel<<<1, 256>>>((const unsigned char*)is_init);            // 1
    mask_kernel<<<(M1 + 255) / 256, 256>>>(is_init);                     // 2
    split_all<<<4096, 256>>>(x, W_ih, W_hh);                             // 3

    gemm_split<128, 128, 4, 2><<<dim3(Gc / 128, M1 / 128), 256, SMEM_BIG>>>(   // 4
        (const __nv_bfloat16*)p_xhi,   (const __nv_bfloat16*)p_xlo,
        (const __nv_bfloat16*)p_wihhi, (const __nv_bfloat16*)p_wihlo,
        b_ih, (float*)p_gi, M1, Gc, Kc);

    init_h_kernel<<<(Bc * Hc + 255) / 256, 256>>>(hx);                   // 5

    for (int t = 0; t < Tc; t++) {                                       // 6..133
        gru_step<<<128, 256, SMEM_STEP>>>(
            (const float*)p_gi,
            (const __nv_bfloat16*)p_whhhi, (const __nv_bfloat16*)p_whhlo,
            b_hh, Hseq, t);
    }

    ln_kernel<<<M1, 128>>>(Hseq, x, ln_g, ln_b, res_gate, Y);            // 134
}

// round 15
// speedup vs baseline: 1.1313x; 1.0314x over previous
#include <cuda_runtime.h>
#include <cuda_bf16.h>
#include <cstdint>
#include <cstddef>

// ---------------------------------------------------------------------------
// Problem constants
// ---------------------------------------------------------------------------
constexpr int Bc = 256;
constexpr int Tc = 128;
constexpr int Dc = 1024;
constexpr int Hc = 1024;
constexpr int Gc = 3 * Hc;        // 3072
constexpr int M1 = Bc * Tc;       // 32768
constexpr int Kc = 1024;

// ---------------------------------------------------------------------------
// Device scratch (static: no cudaMalloc allowed)
// ---------------------------------------------------------------------------
__device__ float         g_gi[(size_t)M1 * Gc];          // x @ W_ih^T + b_ih
__device__ __nv_bfloat16 g_h_hi[2][Bc * Hc];             // double-buffered masked h
__device__ __nv_bfloat16 g_h_lo[2][Bc * Hc];
__device__ __nv_bfloat16 g_x_hi[(size_t)M1 * Dc];
__device__ __nv_bfloat16 g_x_lo[(size_t)M1 * Dc];
__device__ __nv_bfloat16 g_wih_hi[(size_t)Gc * Dc];
__device__ __nv_bfloat16 g_wih_lo[(size_t)Gc * Dc];
__device__ __nv_bfloat16 g_whh_hi[(size_t)Gc * Hc];
__device__ __nv_bfloat16 g_whh_lo[(size_t)Gc * Hc];
__device__ float         g_mask[M1];                     // (~is_init) as float
__device__ int           g_mode;                         // 0=int32, 1=bool8, 2=float32

// ---------------------------------------------------------------------------
// PTX helpers
// ---------------------------------------------------------------------------
__device__ __forceinline__ void cp16(uint32_t s, const void* g) {
    asm volatile("cp.async.cg.shared.global [%0], [%1], 16;" :: "r"(s), "l"(g));
}
__device__ __forceinline__ void ldsm4(uint32_t& r0, uint32_t& r1, uint32_t& r2, uint32_t& r3, uint32_t a) {
    asm volatile("ldmatrix.sync.aligned.m8n8.x4.shared.b16 {%0,%1,%2,%3}, [%4];"
                 : "=r"(r0), "=r"(r1), "=r"(r2), "=r"(r3) : "r"(a));
}
__device__ __forceinline__ void ldsm2(uint32_t& r0, uint32_t& r1, uint32_t a) {
    asm volatile("ldmatrix.sync.aligned.m8n8.x2.shared.b16 {%0,%1}, [%2];"
                 : "=r"(r0), "=r"(r1) : "r"(a));
}
__device__ __forceinline__ void mma16816(float* c, const uint32_t* a, const uint32_t* b) {
    asm volatile("mma.sync.aligned.m16n8k16.row.col.f32.bf16.bf16.f32 "
                 "{%0,%1,%2,%3}, {%4,%5,%6,%7}, {%8,%9}, {%0,%1,%2,%3};"
                 : "+f"(c[0]), "+f"(c[1]), "+f"(c[2]), "+f"(c[3])
                 : "r"(a[0]), "r"(a[1]), "r"(a[2]), "r"(a[3]), "r"(b[0]), "r"(b[1]));
}

// ---------------------------------------------------------------------------
// Split-bf16 GEMM for gi:  C = (Ahi+Alo)[M,K] * (Bhi+Blo)[N,K]^T + bias
// 2-stage pipeline + minBlocksPerSM=2 -> 2 CTAs/SM (163.8KB smem, 64K regs).
// ---------------------------------------------------------------------------
template<int BM, int BN, int WMS, int WNS>
__global__ void __launch_bounds__(WMS * WNS * 32, 2)
gemm_split(const __nv_bfloat16* __restrict__ Ahi, const __nv_bfloat16* __restrict__ Alo,
           const __nv_bfloat16* __restrict__ Bhi, const __nv_bfloat16* __restrict__ Blo,
           const float* __restrict__ bias, float* __restrict__ C,
           int M, int N, int K)
{
    constexpr int NTHR  = WMS * WNS * 32;
    constexpr int WM    = BM / WMS;
    constexpr int WN    = BN / WNS;
    constexpr int MT    = WM / 16;
    constexpr int NT    = WN / 8;
    constexpr int LD    = 40;
    constexpr int TA    = BM * LD;
    constexpr int TB    = BN * LD;
    constexpr int STAGE = 2 * TA + 2 * TB;

    extern __shared__ __align__(16) __nv_bfloat16 smem[];

    const int tid  = threadIdx.x;
    const int lane = tid & 31;
    const int wid  = tid >> 5;
    const int wm   = wid / WNS;
    const int wn   = wid % WNS;
    const int tM   = blockIdx.y * BM;
    const int tN   = blockIdx.x * BN;
    const uint32_t sbase = (uint32_t)__cvta_generic_to_shared(smem);

    auto issue = [&](int kt, int st) {
        const int k0 = kt * 32;
        uint32_t aHi = sbase + (uint32_t)(st * STAGE) * 2u;
        uint32_t aLo = aHi + TA * 2;
        uint32_t bHi = aLo + TA * 2;
        uint32_t bLo = bHi + TB * 2;
        for (int c = tid; c < BM * 4; c += NTHR) {
            int r = c >> 2, q = c & 3;
            size_t go = (size_t)(tM + r) * K + k0 + q * 8;
            uint32_t so = (uint32_t)(r * LD + q * 8) * 2u;
            cp16(aHi + so, Ahi + go);
            cp16(aLo + so, Alo + go);
        }
        for (int c = tid; c < BN * 4; c += NTHR) {
            int r = c >> 2, q = c & 3;
            size_t go = (size_t)(tN + r) * K + k0 + q * 8;
            uint32_t so = (uint32_t)(r * LD + q * 8) * 2u;
            cp16(bHi + so, Bhi + go);
            cp16(bLo + so, Blo + go);
        }
        asm volatile("cp.async.commit_group;");
    };

    float acc[MT][NT][4];
#pragma unroll
    for (int i = 0; i < MT; i++)
#pragma unroll
        for (int j = 0; j < NT; j++)
#pragma unroll
            for (int k = 0; k < 4; k++) acc[i][j][k] = 0.f;

    const int NKT = K / 32;
    issue(0, 0);

    for (int kt = 0; kt < NKT; kt++) {
        const int st = kt & 1;
        if (kt + 1 < NKT) {
            issue(kt + 1, st ^ 1);
            asm volatile("cp.async.wait_group 1;");
        } else {
            asm volatile("cp.async.wait_group 0;");
        }
        __syncthreads();

        uint32_t aHi = sbase + (uint32_t)(st * STAGE) * 2u;
        uint32_t aLo = aHi + TA * 2;
        uint32_t bHi = aLo + TA * 2;
        uint32_t bLo = bHi + TB * 2;

#pragma unroll
        for (int kk = 0; kk < 32; kk += 16) {
            uint32_t ah[MT][4], al[MT][4];
#pragma unroll
            for (int mt = 0; mt < MT; mt++) {
                int row = wm * WM + mt * 16 + (lane & 7) + ((lane >> 3) & 1) * 8;
                int col = kk + (lane >> 4) * 8;
                uint32_t off = (uint32_t)(row * LD + col) * 2u;
                ldsm4(ah[mt][0], ah[mt][1], ah[mt][2], ah[mt][3], aHi + off);
                ldsm4(al[mt][0], al[mt][1], al[mt][2], al[mt][3], aLo + off);
            }
            uint32_t bh[NT][2], bl[NT][2];
#pragma unroll
            for (int p = 0; p < NT / 2; p++) {
                int nrow = wn * WN + p * 16 + ((lane >> 4) << 3) + (lane & 7);
                int kcol = kk + ((lane >> 3) & 1) * 8;
                uint32_t off = (uint32_t)(nrow * LD + kcol) * 2u;
                ldsm4(bh[2 * p][0], bh[2 * p][1], bh[2 * p + 1][0], bh[2 * p + 1][1], bHi + off);
                ldsm4(bl[2 * p][0], bl[2 * p][1], bl[2 * p + 1][0], bl[2 * p + 1][1], bLo + off);
            }
#pragma unroll
            for (int mt = 0; mt < MT; mt++)
#pragma unroll
                for (int nt = 0; nt < NT; nt++) {
                    mma16816(acc[mt][nt], ah[mt], bh[nt]);
                    mma16816(acc[mt][nt], ah[mt], bl[nt]);
                    mma16816(acc[mt][nt], al[mt], bh[nt]);
                }
        }
        __syncthreads();
    }

#pragma unroll
    for (int mt = 0; mt < MT; mt++) {
#pragma unroll
        for (int nt = 0; nt < NT; nt++) {
            int gr = tM + wm * WM + mt * 16 + (lane >> 2);
            int gc = tN + wn * WN + nt * 8 + (lane & 3) * 2;
            float b0 = bias[gc], b1 = bias[gc + 1];
            float2 v0 = make_float2(acc[mt][nt][0] + b0, acc[mt][nt][1] + b1);
            float2 v1 = make_float2(acc[mt][nt][2] + b0, acc[mt][nt][3] + b1);
            *reinterpret_cast<float2*>(C + (size_t)gr * N + gc)       = v0;
            *reinterpret_cast<float2*>(C + (size_t)(gr + 8) * N + gc) = v1;
        }
    }
}

// ---------------------------------------------------------------------------
// Fused GRU step, 16 warps (512 threads), warp grid 4x4 (WM=16, WN=24, NT=3).
// Grid = 128 CTAs. CTA (mi = blockIdx.x>>5, ni = blockIdx.x&31):
//   batch rows [64*mi, 64*mi+64), h-cols [32*ni, 32*ni+32).
// B-tile (96 rows) gathers W_hh rows {g*1024 + 32*ni + j} for g in 0..2.
// Pointwise fused in epilogue; h double-buffered (read t&1, write ^1).
// ---------------------------------------------------------------------------
__global__ void __launch_bounds__(512, 1)
gru_step(const float* __restrict__ gi,
         const __nv_bfloat16* __restrict__ Whi,
         const __nv_bfloat16* __restrict__ Wlo,
         const float* __restrict__ b_hh,
         float* __restrict__ Hseq, int t)
{
    constexpr int LD    = 40;
    constexpr int TA    = 64 * LD;             // 2560 elems
    constexpr int TB    = 96 * LD;             // 3840 elems
    constexpr int STAGE = 2 * TA + 2 * TB;     // 12800 elems per stage
    constexpr int NKT   = Kc / 32;             // 32
    constexpr int CLD   = 104;                 // fp32 C-tile row stride

    extern __shared__ __align__(16) __nv_bfloat16 smem[];
    float* Cs = reinterpret_cast<float*>(smem);   // reused after the k-loop

    const int tid  = threadIdx.x;
    const int lane = tid & 31;
    const int wid  = tid >> 5;
    const int wm   = wid >> 2;                 // 0..3, WM=16
    const int wn   = wid & 3;                  // 0..3, WN=24 (NT=3)
    const int mi   = blockIdx.x >> 5;
    const int ni   = blockIdx.x & 31;
    const int m0   = mi * 64;
    const int j0   = ni * 32;
    const int buf  = t & 1;
    const uint32_t sbase = (uint32_t)__cvta_generic_to_shared(smem);

    const __nv_bfloat16* Ahi = g_h_hi[buf];
    const __nv_bfloat16* Alo = g_h_lo[buf];

    auto issue = [&](int kt, int st) {
        const int k0 = kt * 32;
        uint32_t aHi = sbase + (uint32_t)(st * STAGE) * 2u;
        uint32_t aLo = aHi + TA * 2;
        uint32_t bHi = aLo + TA * 2;
        uint32_t bLo = bHi + TB * 2;
        for (int c = tid; c < 640; c += 512) {
            if (c < 256) {
                int r = c >> 2, q = c & 3;
                size_t go = (size_t)(m0 + r) * Kc + k0 + q * 8;
                uint32_t so = (uint32_t)(r * LD + q * 8) * 2u;
                cp16(aHi + so, Ahi + go);
                cp16(aLo + so, Alo + go);
            } else {
                int cc = c - 256;
                int r = cc >> 2, q = cc & 3;       // r in [0,96)
                int g = r >> 5, jj = r & 31;
                size_t go = (size_t)(g * Hc + j0 + jj) * Kc + k0 + q * 8;
                uint32_t so = (uint32_t)(r * LD + q * 8) * 2u;
                cp16(bHi + so, Whi + go);
                cp16(bLo + so, Wlo + go);
            }
        }
        asm volatile("cp.async.commit_group;");
    };

    float acc[3][4];
#pragma unroll
    for (int j = 0; j < 3; j++)
#pragma unroll
        for (int k = 0; k < 4; k++) acc[j][k] = 0.f;

    issue(0, 0);
    issue(1, 1);

    // ---- preload gi + h for this thread's epilogue lanes (overlaps GEMM) ----
    float p_ir[4], p_iz[4], p_in[4], p_h[4];
#pragma unroll
    for (int i = 0; i < 4; i++) {
        int e  = tid + i * 512;          // [0, 2048)
        int rr = e >> 5, jj = e & 31;
        int b  = m0 + rr, j = j0 + jj;
        size_t gib = ((size_t)b * Tc + t) * Gc + j;
        p_ir[i] = gi[gib];
        p_iz[i] = gi[gib + Hc];
        p_in[i] = gi[gib + 2 * Hc];
        size_t hidx = (size_t)b * Hc + j;
        p_h[i] = __bfloat162float(Ahi[hidx]) + __bfloat162float(Alo[hidx]);
    }

    for (int kt = 0; kt < NKT; kt++) {
        const int st = kt % 3;
        if (kt + 2 < NKT) {
            issue(kt + 2, (kt + 2) % 3);
            asm volatile("cp.async.wait_group 2;");
        } else if (kt + 1 < NKT) {
            asm volatile("cp.async.wait_group 1;");
        } else {
            asm volatile("cp.async.wait_group 0;");
        }
        __syncthreads();

        uint32_t aHi = sbase + (uint32_t)(st * STAGE) * 2u;
        uint32_t aLo = aHi + TA * 2;
        uint32_t bHi = aLo + TA * 2;
        uint32_t bLo = bHi + TB * 2;

#pragma unroll
        for (int kk = 0; kk < 32; kk += 16) {
            uint32_t ah[4], al[4];
            {
                int row = wm * 16 + (lane & 7) + ((lane >> 3) & 1) * 8;
                int col = kk + (lane >> 4) * 8;
                uint32_t off = (uint32_t)(row * LD + col) * 2u;
                ldsm4(ah[0], ah[1], ah[2], ah[3], aHi + off);
                ldsm4(al[0], al[1], al[2], al[3], aLo + off);
            }
            uint32_t bh[3][2], bl[3][2];
            {
                // tiles 0,1 (rows wn*24 .. +16) via x4
                int nrow = wn * 24 + ((lane >> 4) << 3) + (lane & 7);
                int kcol = kk + ((lane >> 3) & 1) * 8;
                uint32_t off = (uint32_t)(nrow * LD + kcol) * 2u;
                ldsm4(bh[0][0], bh[0][1], bh[1][0], bh[1][1], bHi + off);
                ldsm4(bl[0][0], bl[0][1], bl[1][0], bl[1][1], bLo + off);
                // tile 2 (rows wn*24+16 .. +24) via x2 (lanes 0-15 supply addrs)
                int nrow2 = wn * 24 + 16 + (lane & 7);
                int kcol2 = kk + ((lane >> 3) & 1) * 8;
                uint32_t off2 = (uint32_t)(nrow2 * LD + kcol2) * 2u;
                ldsm2(bh[2][0], bh[2][1], bHi + off2);
                ldsm2(bl[2][0], bl[2][1], bLo + off2);
            }
#pragma unroll
            for (int nt = 0; nt < 3; nt++) {
                mma16816(acc[nt], ah, bh[nt]);   // hi*hi
                mma16816(acc[nt], ah, bl[nt]);   // hi*lo
                mma16816(acc[nt], al, bh[nt]);   // lo*hi
            }
        }
        __syncthreads();
    }

    // ---- fused epilogue: acc -> smem C tile -> gates -> h update ----
#pragma unroll
    for (int nt = 0; nt < 3; nt++) {
        int rr = wm * 16 + (lane >> 2);
        int gc = wn * 24 + nt * 8 + (lane & 3) * 2;
        *reinterpret_cast<float2*>(&Cs[rr * CLD + gc])       = make_float2(acc[nt][0], acc[nt][1]);
        *reinterpret_cast<float2*>(&Cs[(rr + 8) * CLD + gc]) = make_float2(acc[nt][2], acc[nt][3]);
    }
    __syncthreads();

#pragma unroll
    for (int i = 0; i < 4; i++) {
        int e  = tid + i * 512;
        int rr = e >> 5, jj = e & 31;
        int b  = m0 + rr, j = j0 + jj;

        float hr = Cs[rr * CLD + jj]      + b_hh[j];
        float hz = Cs[rr * CLD + 32 + jj] + b_hh[Hc + j];
        float hn = Cs[rr * CLD + 64 + jj] + b_hh[2 * Hc + j];

        float h = p_h[i];
        float r = 1.f / (1.f + expf(-(p_ir[i] + hr)));
        float z = 1.f / (1.f + expf(-(p_iz[i] + hz)));
        float n = tanhf(p_in[i] + r * hn);
        float hnew = (1.f - z) * n + z * h;

        Hseq[((size_t)b * Tc + t) * Hc + j] = hnew;

        float m  = (t + 1 < Tc) ? g_mask[b * Tc + t + 1] : 0.f;
        float hm = hnew * m;
        size_t hidx = (size_t)b * Hc + j;
        __nv_bfloat16 hh = __float2bfloat16(hm);
        g_h_hi[buf ^ 1][hidx] = hh;
        g_h_lo[buf ^ 1][hidx] = __float2bfloat16(hm - __bfloat162float(hh));
    }
}

// ---------------------------------------------------------------------------
// Mask dtype detection (is_init may be bool8 / int32 / float32)
// ---------------------------------------------------------------------------
__global__ void detect_kernel(const unsigned char* __restrict__ p) {
    __shared__ int nz_off, f3;
    if (threadIdx.x == 0) { nz_off = 0; f3 = 0; }
    __syncthreads();
    int local_nz = 0, local_f3 = 0;
    for (int i = threadIdx.x; i < M1; i += blockDim.x) {
        unsigned char c = p[i];
        if ((i & 3) != 0 && c) local_nz = 1;
        if ((i & 3) == 3 && c == 0x3F) local_f3 = 1;
    }
    if (local_nz) atomicOr(&nz_off, 1);
    if (local_f3) atomicOr(&f3, 1);
    __syncthreads();
    if (threadIdx.x == 0) g_mode = (!nz_off) ? 0 : (f3 ? 2 : 1);
}

__global__ void mask_kernel(const void* __restrict__ p) {
    int i = blockIdx.x * blockDim.x + threadIdx.x;
    if (i >= M1) return;
    int mode = g_mode;
    int v;
    if (mode == 0)      v = (((const int*)p)[i] != 0);
    else if (mode == 1) v = (((const unsigned char*)p)[i] != 0);
    else                v = (((const float*)p)[i] != 0.f);
    g_mask[i] = v ? 0.f : 1.f;
}

// ---------------------------------------------------------------------------
// Fused fp32 -> (bf16 hi, lo) split for x, W_ih, W_hh (one launch).
// ---------------------------------------------------------------------------
__device__ __forceinline__ void split_range(const float* __restrict__ src,
                                            __nv_bfloat16* __restrict__ hi,
                                            __nv_bfloat16* __restrict__ lo,
                                            long n, long tid0, long stride) {
    for (long i = tid0; i < n; i += stride) {
        float v = src[i];
        __nv_bfloat16 h = __float2bfloat16(v);
        hi[i] = h;
        lo[i] = __float2bfloat16(v - __bfloat162float(h));
    }
}

__global__ void split_all(const float* __restrict__ x,
                          const float* __restrict__ wih,
                          const float* __restrict__ whh) {
    long tid0   = (long)blockIdx.x * blockDim.x + threadIdx.x;
    long stride = (long)gridDim.x * blockDim.x;
    split_range(x,   g_x_hi,   g_x_lo,   (long)M1 * Dc, tid0, stride);
    split_range(wih, g_wih_hi, g_wih_lo, (long)Gc * Dc, tid0, stride);
    split_range(whh, g_whh_hi, g_whh_lo, (long)Gc * Hc, tid0, stride);
}

// ---------------------------------------------------------------------------
// h0 = hx * mask[:,0] -> buffer 0 (bf16 hi/lo)
// ---------------------------------------------------------------------------
__global__ void init_h_kernel(const float* __restrict__ hx) {
    int idx = blockIdx.x * blockDim.x + threadIdx.x;
    if (idx >= Bc * Hc) return;
    int b = idx >> 10;
    float v = hx[idx] * g_mask[(size_t)b * Tc + 0];
    __nv_bfloat16 h = __float2bfloat16(v);
    g_h_hi[0][idx] = h;
    g_h_lo[0][idx] = __float2bfloat16(v - __bfloat162float(h));
}

// ---------------------------------------------------------------------------
// Y = LN(Hseq)*g + b + x*sigmoid(res_gate)
// ---------------------------------------------------------------------------
__global__ void ln_kernel(const float* __restrict__ Hseq, const float* __restrict__ x,
                          const float* __restrict__ gg, const float* __restrict__ bb,
                          const float* __restrict__ res_gate, float* __restrict__ Y) {
    int m = blockIdx.x;
    const float* row = Hseq + (size_t)m * Hc;
    int tid = threadIdx.x;
    int lane = tid & 31, wid = tid >> 5;

    float v[8];
    float s = 0.f, s2 = 0.f;
#pragma unroll
    for (int i = 0; i < 8; i++) {
        float t = row[tid + i * 128];
        v[i] = t; s += t; s2 += t * t;
    }
#pragma unroll
    for (int o = 16; o; o >>= 1) {
        s  += __shfl_xor_sync(0xffffffffu, s, o);
        s2 += __shfl_xor_sync(0xffffffffu, s2, o);
    }
    __shared__ float red[8];
    if (lane == 0) { red[wid] = s; red[4 + wid] = s2; }
    __syncthreads();
    float ts  = red[0] + red[1] + red[2] + red[3];
    float ts2 = red[4] + red[5] + red[6] + red[7];
    float mu  = ts * (1.f / Hc);
    float var = ts2 * (1.f / Hc) - mu * mu;
    float rs  = rsqrtf(var + 1e-5f);

#pragma unroll
    for (int i = 0; i < 8; i++) {
        int j = tid + i * 128;
        float res = 1.f / (1.f + expf(-res_gate[j]));
        Y[(size_t)m * Hc + j] = (v[i] - mu) * rs * gg[j] + bb[j]
                              + x[(size_t)m * Hc + j] * res;
    }
}

// ---------------------------------------------------------------------------
// Launch
// ---------------------------------------------------------------------------
extern "C" void kernel_launch(void* const* d_in, const int* in_sizes, int n_in,
                              void* d_out, int out_size) {
    (void)in_sizes; (void)n_in; (void)out_size;
    const float* x        = (const float*)d_in[0];
    const float* hx       = (const float*)d_in[1];
    const void*  is_init  = d_in[2];
    const float* W_ih     = (const float*)d_in[3];
    const float* W_hh     = (const float*)d_in[4];
    const float* b_ih     = (const float*)d_in[5];
    const float* b_hh     = (const float*)d_in[6];
    const float* ln_g     = (const float*)d_in[7];
    const float* ln_b     = (const float*)d_in[8];
    const float* res_gate = (const float*)d_in[9];

    float* Y    = (float*)d_out;
    float* Hseq = Y + (size_t)M1 * Hc;   // tuple order: (Y, Hseq)

    void *p_gi, *p_xhi, *p_xlo, *p_wihhi, *p_wihlo, *p_whhhi, *p_whhlo;
    cudaGetSymbolAddress(&p_gi,    g_gi);
    cudaGetSymbolAddress(&p_xhi,   g_x_hi);
    cudaGetSymbolAddress(&p_xlo,   g_x_lo);
    cudaGetSymbolAddress(&p_wihhi, g_wih_hi);
    cudaGetSymbolAddress(&p_wihlo, g_wih_lo);
    cudaGetSymbolAddress(&p_whhhi, g_whh_hi);
    cudaGetSymbolAddress(&p_whhlo, g_whh_lo);

    constexpr int SMEM_BIG  = 2 * (2 * 128 * 40 + 2 * 128 * 40) * 2;   // 81920 (2-stage, 2 CTA/SM)
    constexpr int SMEM_STEP = 3 * (2 * 64 * 40 + 2 * 96 * 40) * 2;     // 76800
    cudaFuncSetAttribute(gemm_split<128, 128, 4, 2>,
                         cudaFuncAttributeMaxDynamicSharedMemorySize, SMEM_BIG);
    cudaFuncSetAttribute(gru_step,
                         cudaFuncAttributeMaxDynamicSharedMemorySize, SMEM_STEP);

    detect_kernel<<<1, 256>>>((const unsigned char*)is_init);            // 1
    mask_kernel<<<(M1 + 255) / 256, 256>>>(is_init);                     // 2
    split_all<<<4096, 256>>>(x, W_ih, W_hh);                             // 3

    gemm_split<128, 128, 4, 2><<<dim3(Gc / 128, M1 / 128), 256, SMEM_BIG>>>(   // 4
        (const __nv_bfloat16*)p_xhi,   (const __nv_bfloat16*)p_xlo,
        (const __nv_bfloat16*)p_wihhi, (const __nv_bfloat16*)p_wihlo,
        b_ih, (float*)p_gi, M1, Gc, Kc);

    init_h_kernel<<<(Bc * Hc + 255) / 256, 256>>>(hx);                   // 5

    for (int t = 0; t < Tc; t++) {                                       // 6..133
        gru_step<<<128, 512, SMEM_STEP>>>(
            (const float*)p_gi,
            (const __nv_bfloat16*)p_whhhi, (const __nv_bfloat16*)p_whhlo,
            b_hh, Hseq, t);
    }

    ln_kernel<<<M1, 128>>>(Hseq, x, ln_g, ln_b, res_gate, Y);            // 134
}